// round 1
// baseline (speedup 1.0000x reference)
#include <cuda_runtime.h>
#include <math.h>

#define BB  16
#define CC  512
#define HW  1024
#define GG  32
#define CPG 16
#define EPSV 1e-5f

#define BCHW (BB*CC*HW)      // 8,388,608 floats
#define BNN  (BB*HW*HW)      // 16,777,216 floats

// scratch: gn | q | k | v | hh | scores
__device__ float g_scratch[5*BCHW + BNN];

// ---------------------------------------------------------------------------
// GroupNorm + SiLU.  One block per (b,g); reduce 16*1024 elements.
// ---------------------------------------------------------------------------
__global__ __launch_bounds__(256) void gn_silu_kernel(
    const float* __restrict__ x, const float* __restrict__ gamma,
    const float* __restrict__ beta, float* __restrict__ out)
{
    int bg = blockIdx.x;
    int b = bg / GG, g = bg % GG;
    const float* xp = x   + ((size_t)b*CC + g*CPG)*HW;
    float*       op = out + ((size_t)b*CC + g*CPG)*HW;
    int tid = threadIdx.x;

    float s = 0.f, ss = 0.f;
    for (int i = tid; i < CPG*HW; i += 256) {
        float v = xp[i];
        s += v; ss += v*v;
    }
    __shared__ float sh0[256], sh1[256];
    sh0[tid] = s; sh1[tid] = ss;
    __syncthreads();
    for (int o = 128; o > 0; o >>= 1) {
        if (tid < o) { sh0[tid] += sh0[tid+o]; sh1[tid] += sh1[tid+o]; }
        __syncthreads();
    }
    const float inv_n = 1.f / (float)(CPG*HW);
    float mean = sh0[0] * inv_n;
    float var  = sh1[0] * inv_n - mean*mean;
    float rstd = rsqrtf(var + EPSV);

    for (int i = tid; i < CPG*HW; i += 256) {
        int c = g*CPG + (i >> 10);            // i / HW
        float v = (xp[i] - mean) * rstd * gamma[c] + beta[c];
        op[i] = v / (1.f + __expf(-v));       // SiLU
    }
}

// ---------------------------------------------------------------------------
// GEMM: out[b][m][n] = sum_k W[m][k] * X[b][k][n] + bias[m] (+ res[b][m][n])
// M=512, N=1024, K=512. 64x64 tile, TK=16, 256 threads, 4x4 per thread.
// ---------------------------------------------------------------------------
template<bool RES>
__global__ __launch_bounds__(256) void gemm_wx_kernel(
    const float* __restrict__ W, const float* __restrict__ X,
    const float* __restrict__ bias, const float* __restrict__ res,
    float* __restrict__ out)
{
    int b  = blockIdx.z;
    int m0 = blockIdx.y * 64, n0 = blockIdx.x * 64;
    const float* Xb = X + (size_t)b*CC*HW;
    float*       Ob = out + (size_t)b*CC*HW;

    __shared__ float As[16][65];   // As[kk][mm] (transposed store -> pad)
    __shared__ float Bs[16][64];   // Bs[kk][nn]

    int tid = threadIdx.x;
    int tx = tid & 15, ty = tid >> 4;
    float acc[4][4] = {};

    for (int k0 = 0; k0 < CC; k0 += 16) {
        #pragma unroll
        for (int t = 0; t < 4; t++) {
            int e  = tid + 256*t;
            int mm = e >> 4, kk = e & 15;
            As[kk][mm] = W[(size_t)(m0+mm)*CC + k0 + kk];
            int kk2 = e >> 6, nn = e & 63;
            Bs[kk2][nn] = Xb[(size_t)(k0+kk2)*HW + n0 + nn];
        }
        __syncthreads();
        #pragma unroll
        for (int kk = 0; kk < 16; kk++) {
            float a[4], bv[4];
            #pragma unroll
            for (int i = 0; i < 4; i++) a[i]  = As[kk][ty*4+i];
            #pragma unroll
            for (int j = 0; j < 4; j++) bv[j] = Bs[kk][tx*4+j];
            #pragma unroll
            for (int i = 0; i < 4; i++)
                #pragma unroll
                for (int j = 0; j < 4; j++)
                    acc[i][j] += a[i]*bv[j];
        }
        __syncthreads();
    }

    #pragma unroll
    for (int i = 0; i < 4; i++) {
        int m = m0 + ty*4 + i;
        float bb = bias[m];
        #pragma unroll
        for (int j = 0; j < 4; j++) {
            int n = n0 + tx*4 + j;
            float v = acc[i][j] + bb;
            if (RES) v += res[(size_t)b*CC*HW + (size_t)m*HW + n];
            Ob[(size_t)m*HW + n] = v;
        }
    }
}

// ---------------------------------------------------------------------------
// Scores: s[b][i][j] = scale * sum_c q[b][c][i] * k[b][c][j]
// ---------------------------------------------------------------------------
__global__ __launch_bounds__(256) void scores_kernel(
    const float* __restrict__ q, const float* __restrict__ k,
    float* __restrict__ s, float scale)
{
    int b  = blockIdx.z;
    int i0 = blockIdx.y * 64, j0 = blockIdx.x * 64;
    const float* qb = q + (size_t)b*CC*HW;
    const float* kb = k + (size_t)b*CC*HW;
    float*       sb = s + (size_t)b*HW*HW;

    __shared__ float As[16][64];   // As[kk][ii] = q[k0+kk][i0+ii]
    __shared__ float Bs[16][64];   // Bs[kk][jj] = k[k0+kk][j0+jj]

    int tid = threadIdx.x;
    int tx = tid & 15, ty = tid >> 4;
    float acc[4][4] = {};

    for (int k0 = 0; k0 < CC; k0 += 16) {
        #pragma unroll
        for (int t = 0; t < 4; t++) {
            int e  = tid + 256*t;
            int kk = e >> 6, ii = e & 63;
            As[kk][ii] = qb[(size_t)(k0+kk)*HW + i0 + ii];
            Bs[kk][ii] = kb[(size_t)(k0+kk)*HW + j0 + ii];
        }
        __syncthreads();
        #pragma unroll
        for (int kk = 0; kk < 16; kk++) {
            float a[4], bv[4];
            #pragma unroll
            for (int i = 0; i < 4; i++) a[i]  = As[kk][ty*4+i];
            #pragma unroll
            for (int j = 0; j < 4; j++) bv[j] = Bs[kk][tx*4+j];
            #pragma unroll
            for (int i = 0; i < 4; i++)
                #pragma unroll
                for (int j = 0; j < 4; j++)
                    acc[i][j] += a[i]*bv[j];
        }
        __syncthreads();
    }

    #pragma unroll
    for (int i = 0; i < 4; i++)
        #pragma unroll
        for (int j = 0; j < 4; j++)
            sb[(size_t)(i0+ty*4+i)*HW + j0+tx*4+j] = acc[i][j] * scale;
}

// ---------------------------------------------------------------------------
// Row softmax over j (1024). One block per (b,i) row, in place.
// ---------------------------------------------------------------------------
__global__ __launch_bounds__(256) void softmax_kernel(float* __restrict__ s)
{
    float* sp = s + (size_t)blockIdx.x * HW;
    int tid = threadIdx.x;
    float v[4];
    float m = -1e30f;
    #pragma unroll
    for (int t = 0; t < 4; t++) { v[t] = sp[tid + 256*t]; m = fmaxf(m, v[t]); }

    __shared__ float sh[256];
    sh[tid] = m; __syncthreads();
    for (int o = 128; o > 0; o >>= 1) {
        if (tid < o) sh[tid] = fmaxf(sh[tid], sh[tid+o]);
        __syncthreads();
    }
    m = sh[0];
    __syncthreads();

    float sum = 0.f;
    #pragma unroll
    for (int t = 0; t < 4; t++) { v[t] = __expf(v[t] - m); sum += v[t]; }
    sh[tid] = sum; __syncthreads();
    for (int o = 128; o > 0; o >>= 1) {
        if (tid < o) sh[tid] += sh[tid+o];
        __syncthreads();
    }
    float inv = 1.f / sh[0];
    #pragma unroll
    for (int t = 0; t < 4; t++) sp[tid + 256*t] = v[t] * inv;
}

// ---------------------------------------------------------------------------
// attn @ V: hh[b][c][i] = sum_j v[b][c][j] * attn[b][i][j]
// M=C over c, N=HW over i, K=HW over j.
// ---------------------------------------------------------------------------
__global__ __launch_bounds__(256) void av_kernel(
    const float* __restrict__ v, const float* __restrict__ attn,
    float* __restrict__ hh)
{
    int b  = blockIdx.z;
    int c0 = blockIdx.y * 64, i0 = blockIdx.x * 64;
    const float* vb = v    + (size_t)b*CC*HW;
    const float* ab = attn + (size_t)b*HW*HW;
    float*       hb = hh   + (size_t)b*CC*HW;

    __shared__ float As[16][65];   // As[kk][cc] = v[c0+cc][j0+kk]
    __shared__ float Bs[16][65];   // Bs[kk][ii] = attn[i0+ii][j0+kk]

    int tid = threadIdx.x;
    int tx = tid & 15, ty = tid >> 4;
    float acc[4][4] = {};

    for (int j0 = 0; j0 < HW; j0 += 16) {
        #pragma unroll
        for (int t = 0; t < 4; t++) {
            int e  = tid + 256*t;
            int rr = e >> 4, kk = e & 15;
            As[kk][rr] = vb[(size_t)(c0+rr)*HW + j0 + kk];
            Bs[kk][rr] = ab[(size_t)(i0+rr)*HW + j0 + kk];
        }
        __syncthreads();
        #pragma unroll
        for (int kk = 0; kk < 16; kk++) {
            float a[4], bv[4];
            #pragma unroll
            for (int i = 0; i < 4; i++) a[i]  = As[kk][ty*4+i];
            #pragma unroll
            for (int j = 0; j < 4; j++) bv[j] = Bs[kk][tx*4+j];
            #pragma unroll
            for (int i = 0; i < 4; i++)
                #pragma unroll
                for (int j = 0; j < 4; j++)
                    acc[i][j] += a[i]*bv[j];
        }
        __syncthreads();
    }

    #pragma unroll
    for (int i = 0; i < 4; i++)
        #pragma unroll
        for (int j = 0; j < 4; j++)
            hb[(size_t)(c0+ty*4+i)*HW + i0+tx*4+j] = acc[i][j];
}

// ---------------------------------------------------------------------------
extern "C" void kernel_launch(void* const* d_in, const int* in_sizes, int n_in,
                              void* d_out, int out_size)
{
    const float* x     = (const float*)d_in[0];
    const float* Wq    = (const float*)d_in[1];
    const float* bq    = (const float*)d_in[2];
    const float* Wk    = (const float*)d_in[3];
    const float* bk    = (const float*)d_in[4];
    const float* Wv    = (const float*)d_in[5];
    const float* bv    = (const float*)d_in[6];
    const float* Wo    = (const float*)d_in[7];
    const float* bo    = (const float*)d_in[8];
    const float* gamma = (const float*)d_in[9];
    const float* beta  = (const float*)d_in[10];
    float* out = (float*)d_out;

    float* base = nullptr;
    cudaGetSymbolAddress((void**)&base, g_scratch);
    float* gn = base;
    float* q  = base + 1*(size_t)BCHW;
    float* k  = base + 2*(size_t)BCHW;
    float* v  = base + 3*(size_t)BCHW;
    float* hh = base + 4*(size_t)BCHW;
    float* s  = base + 5*(size_t)BCHW;

    const float scale = 1.0f / sqrtf((float)CC);

    gn_silu_kernel<<<BB*GG, 256>>>(x, gamma, beta, gn);

    dim3 gq(HW/64, CC/64, BB);
    gemm_wx_kernel<false><<<gq, 256>>>(Wq, gn, bq, nullptr, q);
    gemm_wx_kernel<false><<<gq, 256>>>(Wk, gn, bk, nullptr, k);
    gemm_wx_kernel<false><<<gq, 256>>>(Wv, gn, bv, nullptr, v);

    dim3 gs(HW/64, HW/64, BB);
    scores_kernel<<<gs, 256>>>(q, k, s, scale);

    softmax_kernel<<<BB*HW, 256>>>(s);

    dim3 ga(HW/64, CC/64, BB);
    av_kernel<<<ga, 256>>>(v, s, hh);

    gemm_wx_kernel<true><<<gq, 256>>>(Wo, hh, bo, x, out);
}

// round 3
// speedup vs baseline: 1.4627x; 1.4627x over previous
#include <cuda_runtime.h>
#include <cuda_bf16.h>
#include <cstdint>
#include <math.h>

typedef __nv_bfloat16 bf16;

#define BB  16
#define CC  512
#define HW  1024
#define GG  32
#define CPG 16
#define EPSV 1e-5f
#define KP1 1536              // 3*512
#define KP2 3072              // 3*1024

// ---------------------------------------------------------------------------
// Scratch layout (bytes)
// ---------------------------------------------------------------------------
#define SZ_WQKB   ((size_t)1024*1536*2)
#define SZ_WVA    ((size_t)512*1536*2)
#define SZ_WOA    ((size_t)512*1536*2)
#define SZ_BIASQK ((size_t)1024*4)
#define SZ_GNA    ((size_t)BB*1024*1536*2)
#define SZ_GNB    ((size_t)BB*1024*1536*2)
#define SZ_QT     ((size_t)BB*1024*1536*2)
#define SZ_KT     ((size_t)BB*1024*1536*2)
#define SZ_VS     ((size_t)BB*512*3072*2)
#define SZ_ATTN   ((size_t)BB*1024*3072*2)
#define SZ_HHT    ((size_t)BB*1024*1536*2)
#define SZ_S      ((size_t)BB*1024*1024*4)

#define OFF_WQKB   ((size_t)0)
#define OFF_WVA    (OFF_WQKB   + SZ_WQKB)
#define OFF_WOA    (OFF_WVA    + SZ_WVA)
#define OFF_BIASQK (OFF_WOA    + SZ_WOA)
#define OFF_GNA    (OFF_BIASQK + SZ_BIASQK)
#define OFF_GNB    (OFF_GNA    + SZ_GNA)
#define OFF_QT     (OFF_GNB    + SZ_GNB)
#define OFF_KT     (OFF_QT     + SZ_QT)
#define OFF_VS     (OFF_KT     + SZ_KT)
#define OFF_ATTN   (OFF_VS     + SZ_VS)
#define OFF_HHT    (OFF_ATTN   + SZ_ATTN)
#define OFF_S      (OFF_HHT    + SZ_HHT)
#define SCRATCH_BYTES (OFF_S + SZ_S)

__device__ __align__(256) unsigned char g_scratch[SCRATCH_BYTES];

// ---------------------------------------------------------------------------
// PTX helpers (base-target safe: mma.sync / ldmatrix / cp.async)
// ---------------------------------------------------------------------------
__device__ __forceinline__ uint32_t smem_u32(const void* p) {
    uint32_t a;
    asm("{ .reg .u64 t; cvta.to.shared.u64 t, %1; cvt.u32.u64 %0, t; }" : "=r"(a) : "l"(p));
    return a;
}
__device__ __forceinline__ void ldsm4(uint32_t* r, uint32_t addr) {
    asm volatile("ldmatrix.sync.aligned.m8n8.x4.shared.b16 {%0,%1,%2,%3}, [%4];"
                 : "=r"(r[0]), "=r"(r[1]), "=r"(r[2]), "=r"(r[3]) : "r"(addr));
}
__device__ __forceinline__ void mma16816(float* d, const uint32_t* a, const uint32_t* b) {
    asm volatile("mma.sync.aligned.m16n8k16.row.col.f32.bf16.bf16.f32 "
        "{%0,%1,%2,%3}, {%4,%5,%6,%7}, {%8,%9}, {%0,%1,%2,%3};"
        : "+f"(d[0]), "+f"(d[1]), "+f"(d[2]), "+f"(d[3])
        : "r"(a[0]), "r"(a[1]), "r"(a[2]), "r"(a[3]), "r"(b[0]), "r"(b[1]));
}
__device__ __forceinline__ void cpasync16(uint32_t dst, const void* src) {
    asm volatile("cp.async.cg.shared.global [%0], [%1], 16;" :: "r"(dst), "l"(src));
}
#define CP_COMMIT() asm volatile("cp.async.commit_group;" ::: "memory")
#define CP_WAIT1()  asm volatile("cp.async.wait_group 1;" ::: "memory")
#define CP_WAIT0()  asm volatile("cp.async.wait_group 0;" ::: "memory")

// ---------------------------------------------------------------------------
// split-bf16 triads: A-side (h,l,h), B-side (h,h,l)
// ---------------------------------------------------------------------------
__device__ __forceinline__ void split3_A(float v, bf16* d) {
    bf16 h = __float2bfloat16(v);
    bf16 l = __float2bfloat16(v - __bfloat162float(h));
    d[0] = h; d[1] = l; d[2] = h;
}
__device__ __forceinline__ void split3_B(float v, bf16* d) {
    bf16 h = __float2bfloat16(v);
    bf16 l = __float2bfloat16(v - __bfloat162float(h));
    d[0] = h; d[1] = h; d[2] = l;
}
// pair stores (two adjacent columns c, c+1 -> 6 contiguous bf16, 4B-aligned)
__device__ __forceinline__ void store3A2(bf16* p, float v0, float v1) {
    bf16 h0 = __float2bfloat16(v0);
    bf16 l0 = __float2bfloat16(v0 - __bfloat162float(h0));
    bf16 h1 = __float2bfloat16(v1);
    bf16 l1 = __float2bfloat16(v1 - __bfloat162float(h1));
    __nv_bfloat162* q = (__nv_bfloat162*)p;
    q[0] = __halves2bfloat162(h0, l0);
    q[1] = __halves2bfloat162(h0, h1);
    q[2] = __halves2bfloat162(l1, h1);
}
__device__ __forceinline__ void store3B2(bf16* p, float v0, float v1) {
    bf16 h0 = __float2bfloat16(v0);
    bf16 l0 = __float2bfloat16(v0 - __bfloat162float(h0));
    bf16 h1 = __float2bfloat16(v1);
    bf16 l1 = __float2bfloat16(v1 - __bfloat162float(h1));
    __nv_bfloat162* q = (__nv_bfloat162*)p;
    q[0] = __halves2bfloat162(h0, h0);
    q[1] = __halves2bfloat162(l0, h1);
    q[2] = __halves2bfloat162(h1, l1);
}

// ---------------------------------------------------------------------------
// Weight conversion
//   rows 0..1023    : WqkB  (B-side) from Wq|Wk
//   rows 1024..1535 : WvA   (A-side) from Wv
//   rows 1536..2047 : WoA   (A-side) from Wo
//   block 2048      : biasqk = bq|bk
// ---------------------------------------------------------------------------
__global__ __launch_bounds__(256) void convert_w_kernel(
    const float* __restrict__ Wq, const float* __restrict__ Wk,
    const float* __restrict__ Wv, const float* __restrict__ Wo,
    const float* __restrict__ bq, const float* __restrict__ bk,
    bf16* __restrict__ WqkB, bf16* __restrict__ WvA, bf16* __restrict__ WoA,
    float* __restrict__ biasqk)
{
    int r = blockIdx.x;
    int tid = threadIdx.x;
    if (r < 1024) {
        const float* src = (r < 512 ? Wq + (size_t)r*512 : Wk + (size_t)(r-512)*512);
        bf16* dst = WqkB + (size_t)r * 1536;
        for (int k = tid; k < 512; k += 256) split3_B(src[k], dst + 3*k);
    } else if (r < 1536) {
        const float* src = Wv + (size_t)(r-1024)*512;
        bf16* dst = WvA + (size_t)(r-1024) * 1536;
        for (int k = tid; k < 512; k += 256) split3_A(src[k], dst + 3*k);
    } else if (r < 2048) {
        const float* src = Wo + (size_t)(r-1536)*512;
        bf16* dst = WoA + (size_t)(r-1536) * 1536;
        for (int k = tid; k < 512; k += 256) split3_A(src[k], dst + 3*k);
    } else {
        for (int i = tid; i < 1024; i += 256)
            biasqk[i] = (i < 512) ? bq[i] : bk[i-512];
    }
}

// ---------------------------------------------------------------------------
// GroupNorm + SiLU -> gnA [b][n][3c] (A-side) and gnB (B-side)
// ---------------------------------------------------------------------------
__global__ __launch_bounds__(256) void gn_silu_kernel(
    const float* __restrict__ x, const float* __restrict__ gamma,
    const float* __restrict__ beta, bf16* __restrict__ gnA, bf16* __restrict__ gnB)
{
    int bg = blockIdx.x;
    int b = bg / GG, g = bg % GG;
    const float* xp = x + ((size_t)b*CC + g*CPG) * HW;
    int tid = threadIdx.x;

    float s = 0.f, ss = 0.f;
    for (int i = tid; i < CPG*HW; i += 256) {
        float v = xp[i];
        s += v; ss += v*v;
    }
    __shared__ float sh0[256], sh1[256];
    sh0[tid] = s; sh1[tid] = ss;
    __syncthreads();
    for (int o = 128; o > 0; o >>= 1) {
        if (tid < o) { sh0[tid] += sh0[tid+o]; sh1[tid] += sh1[tid+o]; }
        __syncthreads();
    }
    const float inv_n = 1.f / (float)(CPG*HW);
    float mean = sh0[0] * inv_n;
    float var  = sh1[0] * inv_n - mean*mean;
    float rstd = rsqrtf(var + EPSV);

    float gm[CPG], bt[CPG];
    #pragma unroll
    for (int cl = 0; cl < CPG; cl++) { gm[cl] = gamma[g*CPG+cl]; bt[cl] = beta[g*CPG+cl]; }

    for (int n = tid; n < HW; n += 256) {
        bf16* dA = gnA + ((size_t)b*HW + n) * KP1 + (size_t)g*CPG*3;
        bf16* dB = gnB + ((size_t)b*HW + n) * KP1 + (size_t)g*CPG*3;
        #pragma unroll
        for (int cl = 0; cl < CPG; cl++) {
            float v = (xp[cl*HW + n] - mean) * rstd * gm[cl] + bt[cl];
            v = v / (1.f + __expf(-v));
            bf16 h = __float2bfloat16(v);
            bf16 l = __float2bfloat16(v - __bfloat162float(h));
            dA[3*cl] = h; dA[3*cl+1] = l; dA[3*cl+2] = h;
            dB[3*cl] = h; dB[3*cl+1] = h; dB[3*cl+2] = l;
        }
    }
}

// ---------------------------------------------------------------------------
// Row softmax: fp32 scores -> attn split-bf16 A-side [b*i][3072]
// ---------------------------------------------------------------------------
__global__ __launch_bounds__(256) void softmax_kernel(
    const float* __restrict__ s, bf16* __restrict__ attn)
{
    const float* sp = s    + (size_t)blockIdx.x * HW;
    bf16*        ap = attn + (size_t)blockIdx.x * KP2;
    int tid = threadIdx.x;
    float v[4];
    float m = -1e30f;
    #pragma unroll
    for (int t = 0; t < 4; t++) { v[t] = sp[tid + 256*t]; m = fmaxf(m, v[t]); }

    __shared__ float sh[256];
    sh[tid] = m; __syncthreads();
    for (int o = 128; o > 0; o >>= 1) {
        if (tid < o) sh[tid] = fmaxf(sh[tid], sh[tid+o]);
        __syncthreads();
    }
    m = sh[0];
    __syncthreads();

    float sum = 0.f;
    #pragma unroll
    for (int t = 0; t < 4; t++) { v[t] = __expf(v[t] - m); sum += v[t]; }
    sh[tid] = sum; __syncthreads();
    for (int o = 128; o > 0; o >>= 1) {
        if (tid < o) sh[tid] += sh[tid+o];
        __syncthreads();
    }
    float inv = 1.f / sh[0];
    #pragma unroll
    for (int t = 0; t < 4; t++) {
        int j = tid + 256*t;
        split3_A(v[t] * inv, ap + 3*j);
    }
}

// ---------------------------------------------------------------------------
// HMMA GEMM: D[m][n] = sum_k A[m][k'] B[n][k'] over K' (both K-major, split)
// 128x128 CTA tile, 8 warps (4m x 2n), warp tile 32x64, K-chunk 32,
// cp.async double buffer, ldmatrix fragments, m16n8k16 bf16 mma.
// EPI: 0=QK  1=V  2=SCORES  3=AV  4=OUT
// ---------------------------------------------------------------------------
#define STR   40                 // smem row stride in bf16 (32 + 8 pad)
#define ABUFB (128*STR*2)        // bytes per A (or B) stage
#define BUFB  (2*ABUFB)          // bytes per stage (A+B)
#define SMEM_BYTES (2*BUFB)      // double buffered = 40960

template<int EPI>
__global__ __launch_bounds__(256) void hmma_gemm(
    const bf16* __restrict__ A, size_t aStr,
    const bf16* __restrict__ B, size_t bStr, int Kp,
    const float* __restrict__ bias, const float* __restrict__ xres,
    float* __restrict__ fOut, bf16* __restrict__ bOut, bf16* __restrict__ bOut2,
    float scale)
{
    extern __shared__ char smem[];
    const uint32_t sbase = smem_u32(smem);
    const int tid  = threadIdx.x;
    const int lane = tid & 31, wid = tid >> 5;
    const int wm = wid >> 1, wn = wid & 1;
    const int bz = blockIdx.z;
    const int m0 = blockIdx.y * 128, n0 = blockIdx.x * 128;

    const bf16* Ag = A + bz*aStr + (size_t)m0 * Kp;
    const bf16* Bg = B + bz*bStr + (size_t)n0 * Kp;

    // global->smem: each thread 2x16B for A, 2x16B for B
    const int lrow = tid >> 1;
    const int lk   = (tid & 1) * 16;
    const uint32_t dA0 = sbase + (uint32_t)(lrow*STR + lk) * 2;
    const uint32_t dB0 = dA0 + ABUFB;
    const bf16* sA = Ag + (size_t)lrow * Kp + lk;
    const bf16* sB = Bg + (size_t)lrow * Kp + lk;

    // ldmatrix per-thread offsets
    const int aRow = (lane & 15);
    const int aCol = (lane >> 4) * 8;
    const int bRow = (lane & 7) + ((lane >> 4) & 1) * 8;
    const int bCol = ((lane >> 3) & 1) * 8;

    float acc[2][8][4];
    #pragma unroll
    for (int i = 0; i < 2; i++)
        #pragma unroll
        for (int j = 0; j < 8; j++)
            #pragma unroll
            for (int c = 0; c < 4; c++) acc[i][j][c] = 0.f;

    const int nch = Kp >> 5;

    // prologue: chunk 0
    {
        cpasync16(dA0,      sA);
        cpasync16(dA0 + 16, sA + 8);
        cpasync16(dB0,      sB);
        cpasync16(dB0 + 16, sB + 8);
        CP_COMMIT();
    }

    for (int t = 0; t < nch; t++) {
        if (t + 1 < nch) {
            uint32_t off = ((t+1) & 1) * BUFB;
            int kb = (t+1) * 32;
            cpasync16(dA0 + off,      sA + kb);
            cpasync16(dA0 + off + 16, sA + kb + 8);
            cpasync16(dB0 + off,      sB + kb);
            cpasync16(dB0 + off + 16, sB + kb + 8);
            CP_COMMIT();
            CP_WAIT1();
        } else {
            CP_WAIT0();
        }
        __syncthreads();

        const uint32_t abase = sbase + (t & 1) * BUFB;
        const uint32_t bbase = abase + ABUFB;

        #pragma unroll
        for (int ks = 0; ks < 32; ks += 16) {
            uint32_t afr[2][4];
            #pragma unroll
            for (int mf = 0; mf < 2; mf++)
                ldsm4(afr[mf], abase + (uint32_t)((wm*32 + mf*16 + aRow)*STR + ks + aCol) * 2);
            uint32_t bfr[8][2];
            #pragma unroll
            for (int p = 0; p < 4; p++) {
                uint32_t rr[4];
                ldsm4(rr, bbase + (uint32_t)((wn*64 + p*16 + bRow)*STR + ks + bCol) * 2);
                bfr[2*p][0]   = rr[0]; bfr[2*p][1]   = rr[1];
                bfr[2*p+1][0] = rr[2]; bfr[2*p+1][1] = rr[3];
            }
            #pragma unroll
            for (int mf = 0; mf < 2; mf++)
                #pragma unroll
                for (int nf = 0; nf < 8; nf++)
                    mma16816(acc[mf][nf], afr[mf], bfr[nf]);
        }
        __syncthreads();
    }

    // ---------------- epilogue (row-contiguous writes) ----------------
    const int tr = lane >> 2;
    const int tc = (lane & 3) * 2;

    #pragma unroll
    for (int mf = 0; mf < 2; mf++) {
        #pragma unroll
        for (int half = 0; half < 2; half++) {
            int r = m0 + wm*32 + mf*16 + tr + half*8;
            #pragma unroll
            for (int nf = 0; nf < 8; nf++) {
                int c = n0 + wn*64 + nf*8 + tc;
                float d0 = acc[mf][nf][half*2 + 0];
                float d1 = acc[mf][nf][half*2 + 1];

                if (EPI == 0) {                 // QK: D[i][qk-chan]
                    d0 += bias[c]; d1 += bias[c+1];
                    size_t ro = ((size_t)bz*HW + r) * KP1;
                    if (c < 512) store3A2(bOut  + ro + 3*c,        d0, d1);
                    else         store3B2(bOut2 + ro + 3*(c-512),  d0, d1);
                } else if (EPI == 1) {          // V: D[c][i] -> vS[c][3i]
                    float bb = bias[r];
                    store3B2(bOut + ((size_t)bz*CC + r) * KP2 + 3*c, d0+bb, d1+bb);
                } else if (EPI == 2) {          // scores fp32 * scale
                    float2 v = make_float2(d0*scale, d1*scale);
                    *(float2*)(fOut + ((size_t)bz*HW + r) * HW + c) = v;
                } else if (EPI == 3) {          // AV: D[i][c] -> hhT[i][3c]
                    store3B2(bOut + ((size_t)bz*HW + r) * KP1 + 3*c, d0, d1);
                } else {                        // OUT: + bias + residual
                    float bb = bias[r];
                    size_t off = ((size_t)bz*CC + r) * HW + c;
                    float2 xr = *(const float2*)(xres + off);
                    *(float2*)(fOut + off) = make_float2(d0+bb+xr.x, d1+bb+xr.y);
                }
            }
        }
    }
}

// ---------------------------------------------------------------------------
extern "C" void kernel_launch(void* const* d_in, const int* in_sizes, int n_in,
                              void* d_out, int out_size)
{
    const float* x     = (const float*)d_in[0];
    const float* Wq    = (const float*)d_in[1];
    const float* bq    = (const float*)d_in[2];
    const float* Wk    = (const float*)d_in[3];
    const float* bk    = (const float*)d_in[4];
    const float* Wv    = (const float*)d_in[5];
    const float* bv    = (const float*)d_in[6];
    const float* Wo    = (const float*)d_in[7];
    const float* bo    = (const float*)d_in[8];
    const float* gamma = (const float*)d_in[9];
    const float* beta  = (const float*)d_in[10];
    float* out = (float*)d_out;

    unsigned char* base = nullptr;
    cudaGetSymbolAddress((void**)&base, g_scratch);
    bf16*  WqkB   = (bf16*)(base + OFF_WQKB);
    bf16*  WvA    = (bf16*)(base + OFF_WVA);
    bf16*  WoA    = (bf16*)(base + OFF_WOA);
    float* biasqk = (float*)(base + OFF_BIASQK);
    bf16*  gnA    = (bf16*)(base + OFF_GNA);
    bf16*  gnB    = (bf16*)(base + OFF_GNB);
    bf16*  qT     = (bf16*)(base + OFF_QT);
    bf16*  kT     = (bf16*)(base + OFF_KT);
    bf16*  vS     = (bf16*)(base + OFF_VS);
    bf16*  attn   = (bf16*)(base + OFF_ATTN);
    bf16*  hhT    = (bf16*)(base + OFF_HHT);
    float* sS     = (float*)(base + OFF_S);

    const float scale = 1.0f / sqrtf((float)CC);

    convert_w_kernel<<<2049, 256>>>(Wq, Wk, Wv, Wo, bq, bk, WqkB, WvA, WoA, biasqk);
    gn_silu_kernel<<<BB*GG, 256>>>(x, gamma, beta, gnA, gnB);

    // QK: M=1024 pixels (A=gnA), N=1024 q|k channels (B=WqkB), K'=1536
    hmma_gemm<0><<<dim3(8, 8, BB), 256, SMEM_BYTES>>>(
        gnA, (size_t)HW*KP1, WqkB, 0, KP1, biasqk, nullptr, nullptr, qT, kT, 0.f);

    // V: M=512 channels (A=WvA), N=1024 pixels (B=gnB), K'=1536
    hmma_gemm<1><<<dim3(8, 4, BB), 256, SMEM_BYTES>>>(
        WvA, 0, gnB, (size_t)HW*KP1, KP1, bv, nullptr, nullptr, vS, nullptr, 0.f);

    // scores: M=1024 i (A=qT), N=1024 j (B=kT), K'=1536
    hmma_gemm<2><<<dim3(8, 8, BB), 256, SMEM_BYTES>>>(
        qT, (size_t)HW*KP1, kT, (size_t)HW*KP1, KP1, nullptr, nullptr, sS,
        nullptr, nullptr, scale);

    softmax_kernel<<<BB*HW, 256>>>(sS, attn);

    // AV: M=1024 i (A=attn), N=512 c (B=vS), K'=3072
    hmma_gemm<3><<<dim3(4, 8, BB), 256, SMEM_BYTES>>>(
        attn, (size_t)HW*KP2, vS, (size_t)CC*KP2, KP2, nullptr, nullptr, nullptr,
        hhT, nullptr, 0.f);

    // OUT: M=512 c (A=WoA), N=1024 i (B=hhT), K'=1536, + bo + x
    hmma_gemm<4><<<dim3(8, 4, BB), 256, SMEM_BYTES>>>(
        WoA, 0, hhT, (size_t)HW*KP1, KP1, bo, x, out, nullptr, nullptr, 0.f);
}

// round 4
// speedup vs baseline: 1.8993x; 1.2985x over previous
#include <cuda_runtime.h>
#include <cuda_bf16.h>
#include <cstdint>
#include <math.h>

typedef __nv_bfloat16 bf16;

#define BB  16
#define CC  512
#define HW  1024
#define GG  32
#define CPG 16
#define EPSV 1e-5f
#define KP1 1536              // 3*512
#define KP2 3072              // 3*1024

// ---------------------------------------------------------------------------
// Scratch layout (bytes)
// ---------------------------------------------------------------------------
#define SZ_WQKB   ((size_t)1024*1536*2)
#define SZ_WVA    ((size_t)512*1536*2)
#define SZ_WOA    ((size_t)512*1536*2)
#define SZ_BIASQK ((size_t)1024*4)
#define SZ_GNA    ((size_t)BB*1024*1536*2)
#define SZ_GNB    ((size_t)BB*1024*1536*2)
#define SZ_QT     ((size_t)BB*1024*1536*2)
#define SZ_KT     ((size_t)BB*1024*1536*2)
#define SZ_VS     ((size_t)BB*512*3072*2)
#define SZ_ATTN   ((size_t)BB*1024*3072*2)
#define SZ_HHT    ((size_t)BB*1024*1536*2)
#define SZ_S      ((size_t)BB*1024*1024*4)

#define OFF_WQKB   ((size_t)0)
#define OFF_WVA    (OFF_WQKB   + SZ_WQKB)
#define OFF_WOA    (OFF_WVA    + SZ_WVA)
#define OFF_BIASQK (OFF_WOA    + SZ_WOA)
#define OFF_GNA    (OFF_BIASQK + SZ_BIASQK)
#define OFF_GNB    (OFF_GNA    + SZ_GNA)
#define OFF_QT     (OFF_GNB    + SZ_GNB)
#define OFF_KT     (OFF_QT     + SZ_QT)
#define OFF_VS     (OFF_KT     + SZ_KT)
#define OFF_ATTN   (OFF_VS     + SZ_VS)
#define OFF_HHT    (OFF_ATTN   + SZ_ATTN)
#define OFF_S      (OFF_HHT    + SZ_HHT)
#define SCRATCH_BYTES (OFF_S + SZ_S)

__device__ __align__(256) unsigned char g_scratch[SCRATCH_BYTES];

// ---------------------------------------------------------------------------
// PTX helpers (base-target safe: mma.sync / ldmatrix / cp.async)
// ---------------------------------------------------------------------------
__device__ __forceinline__ uint32_t smem_u32(const void* p) {
    uint32_t a;
    asm("{ .reg .u64 t; cvta.to.shared.u64 t, %1; cvt.u32.u64 %0, t; }" : "=r"(a) : "l"(p));
    return a;
}
__device__ __forceinline__ void ldsm4(uint32_t* r, uint32_t addr) {
    asm volatile("ldmatrix.sync.aligned.m8n8.x4.shared.b16 {%0,%1,%2,%3}, [%4];"
                 : "=r"(r[0]), "=r"(r[1]), "=r"(r[2]), "=r"(r[3]) : "r"(addr));
}
__device__ __forceinline__ void mma16816(float* d, const uint32_t* a, const uint32_t* b) {
    asm volatile("mma.sync.aligned.m16n8k16.row.col.f32.bf16.bf16.f32 "
        "{%0,%1,%2,%3}, {%4,%5,%6,%7}, {%8,%9}, {%0,%1,%2,%3};"
        : "+f"(d[0]), "+f"(d[1]), "+f"(d[2]), "+f"(d[3])
        : "r"(a[0]), "r"(a[1]), "r"(a[2]), "r"(a[3]), "r"(b[0]), "r"(b[1]));
}
__device__ __forceinline__ void cpasync16(uint32_t dst, const void* src) {
    asm volatile("cp.async.cg.shared.global [%0], [%1], 16;" :: "r"(dst), "l"(src));
}
#define CP_COMMIT() asm volatile("cp.async.commit_group;" ::: "memory")
#define CP_WAIT1()  asm volatile("cp.async.wait_group 1;" ::: "memory")
#define CP_WAIT0()  asm volatile("cp.async.wait_group 0;" ::: "memory")

// ---------------------------------------------------------------------------
// split-bf16 triads: A-side (h,l,h), B-side (h,h,l)
// ---------------------------------------------------------------------------
__device__ __forceinline__ void split3_A(float v, bf16* d) {
    bf16 h = __float2bfloat16(v);
    bf16 l = __float2bfloat16(v - __bfloat162float(h));
    d[0] = h; d[1] = l; d[2] = h;
}
__device__ __forceinline__ void split3_B(float v, bf16* d) {
    bf16 h = __float2bfloat16(v);
    bf16 l = __float2bfloat16(v - __bfloat162float(h));
    d[0] = h; d[1] = h; d[2] = l;
}
__device__ __forceinline__ void store3A2(bf16* p, float v0, float v1) {
    bf16 h0 = __float2bfloat16(v0);
    bf16 l0 = __float2bfloat16(v0 - __bfloat162float(h0));
    bf16 h1 = __float2bfloat16(v1);
    bf16 l1 = __float2bfloat16(v1 - __bfloat162float(h1));
    __nv_bfloat162* q = (__nv_bfloat162*)p;
    q[0] = __halves2bfloat162(h0, l0);
    q[1] = __halves2bfloat162(h0, h1);
    q[2] = __halves2bfloat162(l1, h1);
}
__device__ __forceinline__ void store3B2(bf16* p, float v0, float v1) {
    bf16 h0 = __float2bfloat16(v0);
    bf16 l0 = __float2bfloat16(v0 - __bfloat162float(h0));
    bf16 h1 = __float2bfloat16(v1);
    bf16 l1 = __float2bfloat16(v1 - __bfloat162float(h1));
    __nv_bfloat162* q = (__nv_bfloat162*)p;
    q[0] = __halves2bfloat162(h0, h0);
    q[1] = __halves2bfloat162(l0, h1);
    q[2] = __halves2bfloat162(h1, l1);
}

// ---------------------------------------------------------------------------
// Weight conversion
// ---------------------------------------------------------------------------
__global__ __launch_bounds__(256) void convert_w_kernel(
    const float* __restrict__ Wq, const float* __restrict__ Wk,
    const float* __restrict__ Wv, const float* __restrict__ Wo,
    const float* __restrict__ bq, const float* __restrict__ bk,
    bf16* __restrict__ WqkB, bf16* __restrict__ WvA, bf16* __restrict__ WoA,
    float* __restrict__ biasqk)
{
    int r = blockIdx.x;
    int tid = threadIdx.x;
    if (r < 1024) {
        const float* src = (r < 512 ? Wq + (size_t)r*512 : Wk + (size_t)(r-512)*512);
        bf16* dst = WqkB + (size_t)r * 1536;
        for (int k = tid; k < 512; k += 256) split3_B(src[k], dst + 3*k);
    } else if (r < 1536) {
        const float* src = Wv + (size_t)(r-1024)*512;
        bf16* dst = WvA + (size_t)(r-1024) * 1536;
        for (int k = tid; k < 512; k += 256) split3_A(src[k], dst + 3*k);
    } else if (r < 2048) {
        const float* src = Wo + (size_t)(r-1536)*512;
        bf16* dst = WoA + (size_t)(r-1536) * 1536;
        for (int k = tid; k < 512; k += 256) split3_A(src[k], dst + 3*k);
    } else {
        for (int i = tid; i < 1024; i += 256)
            biasqk[i] = (i < 512) ? bq[i] : bk[i-512];
    }
}

// ---------------------------------------------------------------------------
// GroupNorm + SiLU -> gnA (A-side) and gnB (B-side), [b][n][3c]
// ---------------------------------------------------------------------------
__global__ __launch_bounds__(256) void gn_silu_kernel(
    const float* __restrict__ x, const float* __restrict__ gamma,
    const float* __restrict__ beta, bf16* __restrict__ gnA, bf16* __restrict__ gnB)
{
    int bg = blockIdx.x;
    int b = bg / GG, g = bg % GG;
    const float* xp = x + ((size_t)b*CC + g*CPG) * HW;
    int tid = threadIdx.x;

    float s = 0.f, ss = 0.f;
    for (int i = tid; i < CPG*HW; i += 256) {
        float v = xp[i];
        s += v; ss += v*v;
    }
    __shared__ float sh0[256], sh1[256];
    sh0[tid] = s; sh1[tid] = ss;
    __syncthreads();
    for (int o = 128; o > 0; o >>= 1) {
        if (tid < o) { sh0[tid] += sh0[tid+o]; sh1[tid] += sh1[tid+o]; }
        __syncthreads();
    }
    const float inv_n = 1.f / (float)(CPG*HW);
    float mean = sh0[0] * inv_n;
    float var  = sh1[0] * inv_n - mean*mean;
    float rstd = rsqrtf(var + EPSV);

    float gm[CPG], bt[CPG];
    #pragma unroll
    for (int cl = 0; cl < CPG; cl++) { gm[cl] = gamma[g*CPG+cl]; bt[cl] = beta[g*CPG+cl]; }

    for (int n = tid; n < HW; n += 256) {
        bf16* dA = gnA + ((size_t)b*HW + n) * KP1 + (size_t)g*CPG*3;
        bf16* dB = gnB + ((size_t)b*HW + n) * KP1 + (size_t)g*CPG*3;
        #pragma unroll
        for (int cl = 0; cl < CPG; cl++) {
            float v = (xp[cl*HW + n] - mean) * rstd * gm[cl] + bt[cl];
            v = v / (1.f + __expf(-v));
            bf16 h = __float2bfloat16(v);
            bf16 l = __float2bfloat16(v - __bfloat162float(h));
            dA[3*cl] = h; dA[3*cl+1] = l; dA[3*cl+2] = h;
            dB[3*cl] = h; dB[3*cl+1] = h; dB[3*cl+2] = l;
        }
    }
}

// ---------------------------------------------------------------------------
// Row softmax -> attn split-bf16 A-side [b*i][3072]
// ---------------------------------------------------------------------------
__global__ __launch_bounds__(256) void softmax_kernel(
    const float* __restrict__ s, bf16* __restrict__ attn)
{
    const float* sp = s    + (size_t)blockIdx.x * HW;
    bf16*        ap = attn + (size_t)blockIdx.x * KP2;
    int tid = threadIdx.x;
    float v[4];
    float m = -1e30f;
    #pragma unroll
    for (int t = 0; t < 4; t++) { v[t] = sp[tid + 256*t]; m = fmaxf(m, v[t]); }

    __shared__ float sh[256];
    sh[tid] = m; __syncthreads();
    for (int o = 128; o > 0; o >>= 1) {
        if (tid < o) sh[tid] = fmaxf(sh[tid], sh[tid+o]);
        __syncthreads();
    }
    m = sh[0];
    __syncthreads();

    float sum = 0.f;
    #pragma unroll
    for (int t = 0; t < 4; t++) { v[t] = __expf(v[t] - m); sum += v[t]; }
    sh[tid] = sum; __syncthreads();
    for (int o = 128; o > 0; o >>= 1) {
        if (tid < o) sh[tid] += sh[tid+o];
        __syncthreads();
    }
    float inv = 1.f / sh[0];
    #pragma unroll
    for (int t = 0; t < 4; t++) {
        int j = tid + 256*t;
        split3_A(v[t] * inv, ap + 3*j);
    }
}

// ---------------------------------------------------------------------------
// HMMA GEMM: D[m][n] = sum_k A[m][k'] B[n][k'], both K-major split-bf16.
// CTA tile 128x128, K-chunk 64, 3-stage cp.async pipeline, XOR-swizzled smem,
// one __syncthreads per chunk. 8 warps (4m x 2n), warp tile 32x64.
// EPI: 0=QK  1=V  2=SCORES  3=AV  4=OUT
// ---------------------------------------------------------------------------
#define KC       64
#define OPB      16384                 // bytes per operand per stage (128*128B)
#define STAGE_B  (2*OPB)               // 32 KB per stage
#define SMEM_BYTES (3*STAGE_B)         // 96 KB

__device__ __forceinline__ void load_stage(uint32_t dst, const bf16* Ag, const bf16* Bg,
                                           int Kp, int k0, int tid)
{
    #pragma unroll
    for (int it = 0; it < 4; it++) {
        int e   = it*256 + tid;        // 0..1023
        int row = e >> 3, grp = e & 7;
        uint32_t off = (uint32_t)(row*128 + ((grp ^ (row & 7)) << 4));
        const bf16* a = Ag + (size_t)row * Kp + k0 + grp*8;
        const bf16* b = Bg + (size_t)row * Kp + k0 + grp*8;
        cpasync16(dst + off, a);
        cpasync16(dst + OPB + off, b);
    }
}

template<int EPI>
__global__ __launch_bounds__(256, 2) void hmma_gemm(
    const bf16* __restrict__ A, size_t aStr,
    const bf16* __restrict__ B, size_t bStr, int Kp,
    const float* __restrict__ bias, const float* __restrict__ xres,
    float* __restrict__ fOut, bf16* __restrict__ bOut, bf16* __restrict__ bOut2,
    float scale)
{
    extern __shared__ char smem[];
    const uint32_t sbase = smem_u32(smem);
    const int tid  = threadIdx.x;
    const int lane = tid & 31, wid = tid >> 5;
    const int wm = wid >> 1, wn = wid & 1;
    const int bz = blockIdx.z;
    const int m0 = blockIdx.y * 128, n0 = blockIdx.x * 128;

    const bf16* Ag = A + bz*aStr + (size_t)m0 * Kp;
    const bf16* Bg = B + bz*bStr + (size_t)n0 * Kp;

    // ldmatrix per-thread geometry (precompute swizzle-invariant parts)
    const int aR0 = wm*32 + (lane & 15);
    const int aGsel = lane >> 4;                          // 0/1
    const int bR0 = wn*64 + (lane & 7) + ((lane >> 4) & 1) * 8;
    const int bGsel = (lane >> 3) & 1;                    // 0/1

    float acc[2][8][4];
    #pragma unroll
    for (int i = 0; i < 2; i++)
        #pragma unroll
        for (int j = 0; j < 8; j++)
            #pragma unroll
            for (int c = 0; c < 4; c++) acc[i][j][c] = 0.f;

    const int nch = Kp >> 6;    // K-chunks of 64

    // prologue: stages 0 and 1 in flight
    load_stage(sbase, Ag, Bg, Kp, 0, tid);
    CP_COMMIT();
    load_stage(sbase + STAGE_B, Ag, Bg, Kp, KC, tid);
    CP_COMMIT();

    int stage = 0;
    for (int t = 0; t < nch; t++) {
        if (t + 2 < nch) CP_WAIT1(); else CP_WAIT0();
        __syncthreads();
        if (t + 2 < nch) {
            int s2 = stage + 2; if (s2 >= 3) s2 -= 3;
            load_stage(sbase + s2*STAGE_B, Ag, Bg, Kp, (t+2)*KC, tid);
            CP_COMMIT();
        }

        const uint32_t abase = sbase + stage*STAGE_B;
        const uint32_t bbase = abase + OPB;

        #pragma unroll
        for (int ks8 = 0; ks8 < 8; ks8 += 2) {
            uint32_t afr[2][4];
            #pragma unroll
            for (int mf = 0; mf < 2; mf++) {
                int r = aR0 + mf*16;
                uint32_t g = (uint32_t)(ks8 + aGsel);
                ldsm4(afr[mf], abase + (uint32_t)(r*128) + ((g ^ (uint32_t)(r & 7)) << 4));
            }
            uint32_t bfr[8][2];
            #pragma unroll
            for (int p = 0; p < 4; p++) {
                int r = bR0 + p*16;
                uint32_t g = (uint32_t)(ks8 + bGsel);
                uint32_t rr[4];
                ldsm4(rr, bbase + (uint32_t)(r*128) + ((g ^ (uint32_t)(r & 7)) << 4));
                bfr[2*p][0]   = rr[0]; bfr[2*p][1]   = rr[1];
                bfr[2*p+1][0] = rr[2]; bfr[2*p+1][1] = rr[3];
            }
            #pragma unroll
            for (int mf = 0; mf < 2; mf++)
                #pragma unroll
                for (int nf = 0; nf < 8; nf++)
                    mma16816(acc[mf][nf], afr[mf], bfr[nf]);
        }

        stage++; if (stage == 3) stage = 0;
    }

    // ---------------- epilogue (row-contiguous writes) ----------------
    const int tr = lane >> 2;
    const int tc = (lane & 3) * 2;

    #pragma unroll
    for (int mf = 0; mf < 2; mf++) {
        #pragma unroll
        for (int half = 0; half < 2; half++) {
            int r = m0 + wm*32 + mf*16 + tr + half*8;
            #pragma unroll
            for (int nf = 0; nf < 8; nf++) {
                int c = n0 + wn*64 + nf*8 + tc;
                float d0 = acc[mf][nf][half*2 + 0];
                float d1 = acc[mf][nf][half*2 + 1];

                if (EPI == 0) {                 // QK: D[i][qk-chan]
                    d0 += bias[c]; d1 += bias[c+1];
                    size_t ro = ((size_t)bz*HW + r) * KP1;
                    if (c < 512) store3A2(bOut  + ro + 3*c,        d0, d1);
                    else         store3B2(bOut2 + ro + 3*(c-512),  d0, d1);
                } else if (EPI == 1) {          // V: D[c][i] -> vS[c][3i]
                    float bb = bias[r];
                    store3B2(bOut + ((size_t)bz*CC + r) * KP2 + 3*c, d0+bb, d1+bb);
                } else if (EPI == 2) {          // scores fp32 * scale
                    float2 v = make_float2(d0*scale, d1*scale);
                    *(float2*)(fOut + ((size_t)bz*HW + r) * HW + c) = v;
                } else if (EPI == 3) {          // AV: D[i][c] -> hhT[i][3c]
                    store3B2(bOut + ((size_t)bz*HW + r) * KP1 + 3*c, d0, d1);
                } else {                        // OUT: + bias + residual
                    float bb = bias[r];
                    size_t off = ((size_t)bz*CC + r) * HW + c;
                    float2 xr = *(const float2*)(xres + off);
                    *(float2*)(fOut + off) = make_float2(d0+bb+xr.x, d1+bb+xr.y);
                }
            }
        }
    }
}

// ---------------------------------------------------------------------------
extern "C" void kernel_launch(void* const* d_in, const int* in_sizes, int n_in,
                              void* d_out, int out_size)
{
    const float* x     = (const float*)d_in[0];
    const float* Wq    = (const float*)d_in[1];
    const float* bq    = (const float*)d_in[2];
    const float* Wk    = (const float*)d_in[3];
    const float* bk    = (const float*)d_in[4];
    const float* Wv    = (const float*)d_in[5];
    const float* bv    = (const float*)d_in[6];
    const float* Wo    = (const float*)d_in[7];
    const float* bo    = (const float*)d_in[8];
    const float* gamma = (const float*)d_in[9];
    const float* beta  = (const float*)d_in[10];
    float* out = (float*)d_out;

    unsigned char* base = nullptr;
    cudaGetSymbolAddress((void**)&base, g_scratch);
    bf16*  WqkB   = (bf16*)(base + OFF_WQKB);
    bf16*  WvA    = (bf16*)(base + OFF_WVA);
    bf16*  WoA    = (bf16*)(base + OFF_WOA);
    float* biasqk = (float*)(base + OFF_BIASQK);
    bf16*  gnA    = (bf16*)(base + OFF_GNA);
    bf16*  gnB    = (bf16*)(base + OFF_GNB);
    bf16*  qT     = (bf16*)(base + OFF_QT);
    bf16*  kT     = (bf16*)(base + OFF_KT);
    bf16*  vS     = (bf16*)(base + OFF_VS);
    bf16*  attn   = (bf16*)(base + OFF_ATTN);
    bf16*  hhT    = (bf16*)(base + OFF_HHT);
    float* sS     = (float*)(base + OFF_S);

    cudaFuncSetAttribute(hmma_gemm<0>, cudaFuncAttributeMaxDynamicSharedMemorySize, SMEM_BYTES);
    cudaFuncSetAttribute(hmma_gemm<1>, cudaFuncAttributeMaxDynamicSharedMemorySize, SMEM_BYTES);
    cudaFuncSetAttribute(hmma_gemm<2>, cudaFuncAttributeMaxDynamicSharedMemorySize, SMEM_BYTES);
    cudaFuncSetAttribute(hmma_gemm<3>, cudaFuncAttributeMaxDynamicSharedMemorySize, SMEM_BYTES);
    cudaFuncSetAttribute(hmma_gemm<4>, cudaFuncAttributeMaxDynamicSharedMemorySize, SMEM_BYTES);

    const float scale = 1.0f / sqrtf((float)CC);

    convert_w_kernel<<<2049, 256>>>(Wq, Wk, Wv, Wo, bq, bk, WqkB, WvA, WoA, biasqk);
    gn_silu_kernel<<<BB*GG, 256>>>(x, gamma, beta, gnA, gnB);

    // QK: M=1024 pixels (A=gnA), N=1024 q|k channels (B=WqkB), K'=1536
    hmma_gemm<0><<<dim3(8, 8, BB), 256, SMEM_BYTES>>>(
        gnA, (size_t)HW*KP1, WqkB, 0, KP1, biasqk, nullptr, nullptr, qT, kT, 0.f);

    // V: M=512 channels (A=WvA), N=1024 pixels (B=gnB), K'=1536
    hmma_gemm<1><<<dim3(8, 4, BB), 256, SMEM_BYTES>>>(
        WvA, 0, gnB, (size_t)HW*KP1, KP1, bv, nullptr, nullptr, vS, nullptr, 0.f);

    // scores: M=1024 i (A=qT), N=1024 j (B=kT), K'=1536
    hmma_gemm<2><<<dim3(8, 8, BB), 256, SMEM_BYTES>>>(
        qT, (size_t)HW*KP1, kT, (size_t)HW*KP1, KP1, nullptr, nullptr, sS,
        nullptr, nullptr, scale);

    softmax_kernel<<<BB*HW, 256>>>(sS, attn);

    // AV: M=1024 i (A=attn), N=512 c (B=vS), K'=3072
    hmma_gemm<3><<<dim3(4, 8, BB), 256, SMEM_BYTES>>>(
        attn, (size_t)HW*KP2, vS, (size_t)CC*KP2, KP2, nullptr, nullptr, nullptr,
        hhT, nullptr, 0.f);

    // OUT: M=512 c (A=WoA), N=1024 i (B=hhT), K'=1536, + bo + x
    hmma_gemm<4><<<dim3(8, 4, BB), 256, SMEM_BYTES>>>(
        WoA, 0, hhT, (size_t)HW*KP1, KP1, bo, x, out, nullptr, nullptr, 0.f);
}

// round 5
// speedup vs baseline: 3.3531x; 1.7654x over previous
#include <cuda_runtime.h>
#include <cuda_bf16.h>
#include <cstdint>
#include <math.h>

typedef __nv_bfloat16 bf16;

#define BB  16
#define CC  512
#define HW  1024
#define GG  32
#define CPG 16
#define EPSV 1e-5f

// ---------------------------------------------------------------------------
// Scratch: all bf16 tensors stored as H and L planes.
// ---------------------------------------------------------------------------
#define PL_W    ((size_t)2048*512)          // Wq|Wk|Wv|Wo rows x 512
#define PL_GN   ((size_t)BB*HW*512)
#define PL_Q    ((size_t)BB*HW*512)
#define PL_K    ((size_t)BB*HW*512)
#define PL_V    ((size_t)BB*CC*HW)          // [b][c][i]
#define PL_ATT  ((size_t)BB*HW*HW)          // [b][i][j]
#define PL_HH   ((size_t)BB*HW*512)         // [b][i][c]

#define OFF_WH   ((size_t)0)
#define OFF_WL   (OFF_WH  + PL_W*2)
#define OFF_GNH  (OFF_WL  + PL_W*2)
#define OFF_GNL  (OFF_GNH + PL_GN*2)
#define OFF_QH   (OFF_GNL + PL_GN*2)
#define OFF_QL   (OFF_QH  + PL_Q*2)
#define OFF_KH   (OFF_QL  + PL_Q*2)
#define OFF_KL   (OFF_KH  + PL_K*2)
#define OFF_VH   (OFF_KL  + PL_K*2)
#define OFF_VL   (OFF_VH  + PL_V*2)
#define OFF_AH   (OFF_VL  + PL_V*2)
#define OFF_AL   (OFF_AH  + PL_ATT*2)
#define OFF_HHH  (OFF_AL  + PL_ATT*2)
#define OFF_HHL  (OFF_HHH + PL_HH*2)
#define OFF_S    (OFF_HHL + PL_HH*2)
#define SZ_S     ((size_t)BB*HW*HW*4)
#define SCRATCH_BYTES (OFF_S + SZ_S)

__device__ __align__(256) unsigned char g_scratch[SCRATCH_BYTES];

// ---------------------------------------------------------------------------
// PTX helpers
// ---------------------------------------------------------------------------
__device__ __forceinline__ uint32_t smem_u32(const void* p) {
    uint32_t a;
    asm("{ .reg .u64 t; cvta.to.shared.u64 t, %1; cvt.u32.u64 %0, t; }" : "=r"(a) : "l"(p));
    return a;
}
__device__ __forceinline__ void ldsm4(uint32_t* r, uint32_t addr) {
    asm volatile("ldmatrix.sync.aligned.m8n8.x4.shared.b16 {%0,%1,%2,%3}, [%4];"
                 : "=r"(r[0]), "=r"(r[1]), "=r"(r[2]), "=r"(r[3]) : "r"(addr));
}
__device__ __forceinline__ void mma16816(float* d, const uint32_t* a, const uint32_t* b) {
    asm volatile("mma.sync.aligned.m16n8k16.row.col.f32.bf16.bf16.f32 "
        "{%0,%1,%2,%3}, {%4,%5,%6,%7}, {%8,%9}, {%0,%1,%2,%3};"
        : "+f"(d[0]), "+f"(d[1]), "+f"(d[2]), "+f"(d[3])
        : "r"(a[0]), "r"(a[1]), "r"(a[2]), "r"(a[3]), "r"(b[0]), "r"(b[1]));
}
__device__ __forceinline__ void cpasync16(uint32_t dst, const void* src) {
    asm volatile("cp.async.cg.shared.global [%0], [%1], 16;" :: "r"(dst), "l"(src));
}
#define CP_COMMIT() asm volatile("cp.async.commit_group;" ::: "memory")
#define CP_WAIT1()  asm volatile("cp.async.wait_group 1;" ::: "memory")
#define CP_WAIT0()  asm volatile("cp.async.wait_group 0;" ::: "memory")

// ---------------------------------------------------------------------------
// H/L split helpers
// ---------------------------------------------------------------------------
__device__ __forceinline__ void splitHL(float v, bf16& h, bf16& l) {
    h = __float2bfloat16(v);
    l = __float2bfloat16(v - __bfloat162float(h));
}
__device__ __forceinline__ void storeHL2(bf16* ph, bf16* pl, float v0, float v1) {
    bf16 h0, l0, h1, l1;
    splitHL(v0, h0, l0);
    splitHL(v1, h1, l1);
    *(__nv_bfloat162*)ph = __halves2bfloat162(h0, h1);
    *(__nv_bfloat162*)pl = __halves2bfloat162(l0, l1);
}

// ---------------------------------------------------------------------------
// Weight conversion: rows 0-511 Wq, 512-1023 Wk, 1024-1535 Wv, 1536-2047 Wo
// ---------------------------------------------------------------------------
__global__ __launch_bounds__(256) void convert_w_kernel(
    const float* __restrict__ Wq, const float* __restrict__ Wk,
    const float* __restrict__ Wv, const float* __restrict__ Wo,
    bf16* __restrict__ WH, bf16* __restrict__ WL)
{
    int r = blockIdx.x;
    int tid = threadIdx.x;
    const float* src = (r < 512)  ? Wq + (size_t)r * 512
                     : (r < 1024) ? Wk + (size_t)(r-512) * 512
                     : (r < 1536) ? Wv + (size_t)(r-1024) * 512
                                  : Wo + (size_t)(r-1536) * 512;
    bf16* dh = WH + (size_t)r * 512;
    bf16* dl = WL + (size_t)r * 512;
    for (int k = tid; k < 512; k += 256) {
        bf16 h, l; splitHL(src[k], h, l);
        dh[k] = h; dl[k] = l;
    }
}

// ---------------------------------------------------------------------------
// GroupNorm + SiLU -> gn planes [b][n][512]
// ---------------------------------------------------------------------------
__global__ __launch_bounds__(256) void gn_silu_kernel(
    const float* __restrict__ x, const float* __restrict__ gamma,
    const float* __restrict__ beta, bf16* __restrict__ gnH, bf16* __restrict__ gnL)
{
    int bg = blockIdx.x;
    int b = bg / GG, g = bg % GG;
    const float* xp = x + ((size_t)b*CC + g*CPG) * HW;
    int tid = threadIdx.x;

    float s = 0.f, ss = 0.f;
    for (int i = tid; i < CPG*HW; i += 256) {
        float v = xp[i];
        s += v; ss += v*v;
    }
    __shared__ float sh0[256], sh1[256];
    sh0[tid] = s; sh1[tid] = ss;
    __syncthreads();
    for (int o = 128; o > 0; o >>= 1) {
        if (tid < o) { sh0[tid] += sh0[tid+o]; sh1[tid] += sh1[tid+o]; }
        __syncthreads();
    }
    const float inv_n = 1.f / (float)(CPG*HW);
    float mean = sh0[0] * inv_n;
    float var  = sh1[0] * inv_n - mean*mean;
    float rstd = rsqrtf(var + EPSV);

    float gm[CPG], bt[CPG];
    #pragma unroll
    for (int cl = 0; cl < CPG; cl++) { gm[cl] = gamma[g*CPG+cl]; bt[cl] = beta[g*CPG+cl]; }

    for (int n = tid; n < HW; n += 256) {
        size_t off = ((size_t)b*HW + n) * 512 + g*CPG;
        bf16* dh = gnH + off;
        bf16* dl = gnL + off;
        #pragma unroll
        for (int cl = 0; cl < CPG; cl += 2) {
            float v0 = (xp[cl*HW + n]     - mean) * rstd * gm[cl]   + bt[cl];
            float v1 = (xp[(cl+1)*HW + n] - mean) * rstd * gm[cl+1] + bt[cl+1];
            v0 = v0 / (1.f + __expf(-v0));
            v1 = v1 / (1.f + __expf(-v1));
            storeHL2(dh + cl, dl + cl, v0, v1);
        }
    }
}

// ---------------------------------------------------------------------------
// Row softmax -> attn planes [b*i][1024]
// ---------------------------------------------------------------------------
__global__ __launch_bounds__(256) void softmax_kernel(
    const float* __restrict__ s, bf16* __restrict__ aH, bf16* __restrict__ aL)
{
    const float* sp = s + (size_t)blockIdx.x * HW;
    size_t ro = (size_t)blockIdx.x * HW;
    int tid = threadIdx.x;
    float4 v = *(const float4*)(sp + tid*4);
    float m = fmaxf(fmaxf(v.x, v.y), fmaxf(v.z, v.w));

    __shared__ float sh[256];
    sh[tid] = m; __syncthreads();
    for (int o = 128; o > 0; o >>= 1) {
        if (tid < o) sh[tid] = fmaxf(sh[tid], sh[tid+o]);
        __syncthreads();
    }
    m = sh[0];
    __syncthreads();

    v.x = __expf(v.x - m); v.y = __expf(v.y - m);
    v.z = __expf(v.z - m); v.w = __expf(v.w - m);
    sh[tid] = v.x + v.y + v.z + v.w; __syncthreads();
    for (int o = 128; o > 0; o >>= 1) {
        if (tid < o) sh[tid] += sh[tid+o];
        __syncthreads();
    }
    float inv = 1.f / sh[0];
    storeHL2(aH + ro + tid*4,     aL + ro + tid*4,     v.x*inv, v.y*inv);
    storeHL2(aH + ro + tid*4 + 2, aL + ro + tid*4 + 2, v.z*inv, v.w*inv);
}

// ---------------------------------------------------------------------------
// HMMA GEMM over H/L planes, 3-segment schedule:
//   seg0: A_H x B_H,  seg1: A_L x B_H,  seg2: A_H x B_L
// CTA tile 128x128, 4 warps (2x2), warp tile 64x64, K-chunk 64,
// 3-stage cp.async pipeline, XOR-swizzled smem.
// EPI: 0=QK  1=V  2=SCORES  3=AV  4=OUT
// ---------------------------------------------------------------------------
#define KC       64
#define OPB      16384                 // 128 rows * 128 B
#define STAGE_B  (2*OPB)               // 32 KB
#define SMEM_BYTES (3*STAGE_B)         // 96 KB

__device__ __forceinline__ void load_stage(uint32_t dst, const bf16* Ap, const bf16* Bp,
                                           int Kb, int tid)
{
    #pragma unroll
    for (int it = 0; it < 8; it++) {
        int e   = it*128 + tid;        // 0..1023
        int row = e >> 3, grp = e & 7;
        uint32_t off = (uint32_t)(row*128 + ((grp ^ (row & 7)) << 4));
        cpasync16(dst + off,       Ap + (size_t)row * Kb + grp*8);
        cpasync16(dst + OPB + off, Bp + (size_t)row * Kb + grp*8);
    }
}

template<int EPI>
__global__ __launch_bounds__(128, 2) void hmma_gemm(
    const bf16* __restrict__ AH, const bf16* __restrict__ AL, size_t aStr,
    const bf16* __restrict__ BH, const bf16* __restrict__ BL, size_t bStr, int Kb,
    const float* __restrict__ bias, const float* __restrict__ bias2,
    const float* __restrict__ xres,
    float* __restrict__ fOut, bf16* __restrict__ oH, bf16* __restrict__ oL,
    bf16* __restrict__ o2H, bf16* __restrict__ o2L, float scale)
{
    extern __shared__ char smem[];
    const uint32_t sbase = smem_u32(smem);
    const int tid  = threadIdx.x;
    const int lane = tid & 31, wid = tid >> 5;
    const int wm = wid >> 1, wn = wid & 1;
    const int bz = blockIdx.z;
    const int m0 = blockIdx.y * 128, n0 = blockIdx.x * 128;

    const bf16* AHb = AH + bz*aStr + (size_t)m0 * Kb;
    const bf16* ALb = AL + bz*aStr + (size_t)m0 * Kb;
    const bf16* BHb = BH + bz*bStr + (size_t)n0 * Kb;
    const bf16* BLb = BL + bz*bStr + (size_t)n0 * Kb;

    const int ncb = Kb >> 6;           // chunks per segment
    const int nch = 3 * ncb;

    // ldmatrix per-thread geometry
    const int aR0 = wm*64 + (lane & 15);
    const int aGs = lane >> 4;
    const int bR0 = wn*64 + (lane & 7) + ((lane >> 4) & 1) * 8;
    const int bGs = (lane >> 3) & 1;

    float acc[4][8][4];
    #pragma unroll
    for (int i = 0; i < 4; i++)
        #pragma unroll
        for (int j = 0; j < 8; j++)
            #pragma unroll
            for (int c = 0; c < 4; c++) acc[i][j][c] = 0.f;

    // prologue: chunks 0,1 (both in segment 0 since ncb>=8)
    load_stage(sbase,           AHb, BHb, Kb, tid);  CP_COMMIT();
    load_stage(sbase + STAGE_B, AHb + KC, BHb + KC, Kb, tid);  CP_COMMIT();

    int stage = 0;
    for (int t = 0; t < nch; t++) {
        if (t + 2 < nch) CP_WAIT1(); else CP_WAIT0();
        __syncthreads();
        if (t + 2 < nch) {
            int u = t + 2;
            int seg = (u >= 2*ncb) ? 2 : (u >= ncb ? 1 : 0);
            int kk  = (u - seg*ncb) * KC;
            const bf16* Ap = (seg == 1 ? ALb : AHb) + kk;
            const bf16* Bp = (seg == 2 ? BLb : BHb) + kk;
            int s2 = stage + 2; if (s2 >= 3) s2 -= 3;
            load_stage(sbase + s2*STAGE_B, Ap, Bp, Kb, tid);
            CP_COMMIT();
        }

        const uint32_t abase = sbase + stage*STAGE_B;
        const uint32_t bbase = abase + OPB;

        #pragma unroll
        for (int ks8 = 0; ks8 < 8; ks8 += 2) {
            uint32_t afr[4][4];
            #pragma unroll
            for (int mf = 0; mf < 4; mf++) {
                int r = aR0 + mf*16;
                uint32_t g = (uint32_t)(ks8 + aGs);
                ldsm4(afr[mf], abase + (uint32_t)(r*128) + ((g ^ (uint32_t)(r & 7)) << 4));
            }
            uint32_t bfr[8][2];
            #pragma unroll
            for (int p = 0; p < 4; p++) {
                int r = bR0 + p*16;
                uint32_t g = (uint32_t)(ks8 + bGs);
                uint32_t rr[4];
                ldsm4(rr, bbase + (uint32_t)(r*128) + ((g ^ (uint32_t)(r & 7)) << 4));
                bfr[2*p][0]   = rr[0]; bfr[2*p][1]   = rr[1];
                bfr[2*p+1][0] = rr[2]; bfr[2*p+1][1] = rr[3];
            }
            #pragma unroll
            for (int mf = 0; mf < 4; mf++)
                #pragma unroll
                for (int nf = 0; nf < 8; nf++)
                    mma16816(acc[mf][nf], afr[mf], bfr[nf]);
        }

        stage++; if (stage == 3) stage = 0;
    }

    // ---------------- epilogue ----------------
    const int tr = lane >> 2;
    const int tc = (lane & 3) * 2;

    #pragma unroll
    for (int mf = 0; mf < 4; mf++) {
        #pragma unroll
        for (int half = 0; half < 2; half++) {
            int r = m0 + wm*64 + mf*16 + tr + half*8;
            #pragma unroll
            for (int nf = 0; nf < 8; nf++) {
                int c = n0 + wn*64 + nf*8 + tc;
                float d0 = acc[mf][nf][half*2 + 0];
                float d1 = acc[mf][nf][half*2 + 1];

                if (EPI == 0) {                 // QK: D[i][ch], ch<512 q else k
                    if (c < 512) {
                        d0 += bias[c]; d1 += bias[c+1];
                        size_t idx = ((size_t)bz*HW + r) * 512 + c;
                        storeHL2(oH + idx, oL + idx, d0, d1);
                    } else {
                        d0 += bias2[c-512]; d1 += bias2[c-511];
                        size_t idx = ((size_t)bz*HW + r) * 512 + (c - 512);
                        storeHL2(o2H + idx, o2L + idx, d0, d1);
                    }
                } else if (EPI == 1) {          // V: D[ch][i] -> v planes [ch][i]
                    float bb = bias[r];
                    size_t idx = ((size_t)bz*CC + r) * HW + c;
                    storeHL2(oH + idx, oL + idx, d0+bb, d1+bb);
                } else if (EPI == 2) {          // scores fp32 * scale
                    *(float2*)(fOut + ((size_t)bz*HW + r) * HW + c)
                        = make_float2(d0*scale, d1*scale);
                } else if (EPI == 3) {          // AV: D[i][ch] -> hh planes
                    size_t idx = ((size_t)bz*HW + r) * 512 + c;
                    storeHL2(oH + idx, oL + idx, d0, d1);
                } else {                        // OUT: + bias + residual
                    float bb = bias[r];
                    size_t off = ((size_t)bz*CC + r) * HW + c;
                    float2 xr = *(const float2*)(xres + off);
                    *(float2*)(fOut + off) = make_float2(d0+bb+xr.x, d1+bb+xr.y);
                }
            }
        }
    }
}

// ---------------------------------------------------------------------------
extern "C" void kernel_launch(void* const* d_in, const int* in_sizes, int n_in,
                              void* d_out, int out_size)
{
    const float* x     = (const float*)d_in[0];
    const float* Wq    = (const float*)d_in[1];
    const float* bq    = (const float*)d_in[2];
    const float* Wk    = (const float*)d_in[3];
    const float* bk    = (const float*)d_in[4];
    const float* Wv    = (const float*)d_in[5];
    const float* bv    = (const float*)d_in[6];
    const float* Wo    = (const float*)d_in[7];
    const float* bo    = (const float*)d_in[8];
    const float* gamma = (const float*)d_in[9];
    const float* beta  = (const float*)d_in[10];
    float* out = (float*)d_out;

    unsigned char* base = nullptr;
    cudaGetSymbolAddress((void**)&base, g_scratch);
    bf16*  WH  = (bf16*)(base + OFF_WH);
    bf16*  WL  = (bf16*)(base + OFF_WL);
    bf16*  gnH = (bf16*)(base + OFF_GNH);
    bf16*  gnL = (bf16*)(base + OFF_GNL);
    bf16*  qH  = (bf16*)(base + OFF_QH);
    bf16*  qL  = (bf16*)(base + OFF_QL);
    bf16*  kH  = (bf16*)(base + OFF_KH);
    bf16*  kL  = (bf16*)(base + OFF_KL);
    bf16*  vH  = (bf16*)(base + OFF_VH);
    bf16*  vL  = (bf16*)(base + OFF_VL);
    bf16*  aH  = (bf16*)(base + OFF_AH);
    bf16*  aL  = (bf16*)(base + OFF_AL);
    bf16*  hhH = (bf16*)(base + OFF_HHH);
    bf16*  hhL = (bf16*)(base + OFF_HHL);
    float* sS  = (float*)(base + OFF_S);

    cudaFuncSetAttribute(hmma_gemm<0>, cudaFuncAttributeMaxDynamicSharedMemorySize, SMEM_BYTES);
    cudaFuncSetAttribute(hmma_gemm<1>, cudaFuncAttributeMaxDynamicSharedMemorySize, SMEM_BYTES);
    cudaFuncSetAttribute(hmma_gemm<2>, cudaFuncAttributeMaxDynamicSharedMemorySize, SMEM_BYTES);
    cudaFuncSetAttribute(hmma_gemm<3>, cudaFuncAttributeMaxDynamicSharedMemorySize, SMEM_BYTES);
    cudaFuncSetAttribute(hmma_gemm<4>, cudaFuncAttributeMaxDynamicSharedMemorySize, SMEM_BYTES);

    const float scale = 1.0f / sqrtf((float)CC);

    convert_w_kernel<<<2048, 256>>>(Wq, Wk, Wv, Wo, WH, WL);
    gn_silu_kernel<<<BB*GG, 256>>>(x, gamma, beta, gnH, gnL);

    const size_t PXS = (size_t)HW * 512;   // pixel-row plane stride (per b)
    const size_t CHS = (size_t)CC * HW;    // channel-row plane stride (per b)

    // QK: M=1024 pixels (A=gn), N=1024 q|k rows (B=W rows 0..1023), K=512
    hmma_gemm<0><<<dim3(8, 8, BB), 128, SMEM_BYTES>>>(
        gnH, gnL, PXS, WH, WL, 0, 512, bq, bk, nullptr,
        nullptr, qH, qL, kH, kL, 0.f);

    // V: M=512 channels (A=W rows 1024..1535), N=1024 pixels (B=gn), K=512
    hmma_gemm<1><<<dim3(8, 4, BB), 128, SMEM_BYTES>>>(
        WH + (size_t)1024*512, WL + (size_t)1024*512, 0, gnH, gnL, PXS, 512,
        bv, nullptr, nullptr, nullptr, vH, vL, nullptr, nullptr, 0.f);

    // scores: M=1024 i (A=q), N=1024 j (B=k), K=512 -> fp32 * scale
    hmma_gemm<2><<<dim3(8, 8, BB), 128, SMEM_BYTES>>>(
        qH, qL, PXS, kH, kL, PXS, 512, nullptr, nullptr, nullptr,
        sS, nullptr, nullptr, nullptr, nullptr, scale);

    softmax_kernel<<<BB*HW, 256>>>(sS, aH, aL);

    // AV: M=1024 i (A=attn), N=512 ch (B=v), K=1024 -> hh planes
    hmma_gemm<3><<<dim3(4, 8, BB), 128, SMEM_BYTES>>>(
        aH, aL, (size_t)HW*HW, vH, vL, CHS, 1024, nullptr, nullptr, nullptr,
        nullptr, hhH, hhL, nullptr, nullptr, 0.f);

    // OUT: M=512 ch (A=W rows 1536..2047), N=1024 i (B=hh), K=512, +bo +x
    hmma_gemm<4><<<dim3(8, 4, BB), 128, SMEM_BYTES>>>(
        WH + (size_t)1536*512, WL + (size_t)1536*512, 0, hhH, hhL, PXS, 512,
        bo, nullptr, x, out, nullptr, nullptr, nullptr, nullptr, 0.f);
}

// round 6
// speedup vs baseline: 4.5574x; 1.3592x over previous
#include <cuda_runtime.h>
#include <cuda_fp16.h>
#include <cstdint>
#include <math.h>

typedef __half fp16;

#define BB  16
#define CC  512
#define HW  1024
#define GG  32
#define CPG 16
#define EPSV 1e-5f

// ---------------------------------------------------------------------------
// Scratch: fp16 tensors as H (and where A-side, L) planes.
// ---------------------------------------------------------------------------
#define PL_W    ((size_t)2048*512)          // Wq|Wk|Wv|Wo rows x 512
#define PL_GN   ((size_t)BB*HW*512)
#define PL_Q    ((size_t)BB*HW*512)
#define PL_K    ((size_t)BB*HW*512)
#define PL_V    ((size_t)BB*CC*HW)          // [b][c][i]
#define PL_ATT  ((size_t)BB*HW*HW)          // [b][i][j]
#define PL_HH   ((size_t)BB*HW*512)         // [b][i][c]

#define OFF_WH   ((size_t)0)
#define OFF_WL   (OFF_WH  + PL_W*2)
#define OFF_GNH  (OFF_WL  + PL_W*2)
#define OFF_GNL  (OFF_GNH + PL_GN*2)
#define OFF_QH   (OFF_GNL + PL_GN*2)
#define OFF_QL   (OFF_QH  + PL_Q*2)
#define OFF_KH   (OFF_QL  + PL_Q*2)
#define OFF_VH   (OFF_KH  + PL_K*2)
#define OFF_AH   (OFF_VH  + PL_V*2)
#define OFF_AL   (OFF_AH  + PL_ATT*2)
#define OFF_HHH  (OFF_AL  + PL_ATT*2)
#define OFF_S    (OFF_HHH + PL_HH*2)
#define SZ_S     ((size_t)BB*HW*HW*4)
#define SCRATCH_BYTES (OFF_S + SZ_S)

__device__ __align__(256) unsigned char g_scratch[SCRATCH_BYTES];

// ---------------------------------------------------------------------------
// PTX helpers
// ---------------------------------------------------------------------------
__device__ __forceinline__ uint32_t smem_u32(const void* p) {
    uint32_t a;
    asm("{ .reg .u64 t; cvta.to.shared.u64 t, %1; cvt.u32.u64 %0, t; }" : "=r"(a) : "l"(p));
    return a;
}
__device__ __forceinline__ void ldsm4(uint32_t* r, uint32_t addr) {
    asm volatile("ldmatrix.sync.aligned.m8n8.x4.shared.b16 {%0,%1,%2,%3}, [%4];"
                 : "=r"(r[0]), "=r"(r[1]), "=r"(r[2]), "=r"(r[3]) : "r"(addr));
}
__device__ __forceinline__ void mma16816(float* d, const uint32_t* a, const uint32_t* b) {
    asm volatile("mma.sync.aligned.m16n8k16.row.col.f32.f16.f16.f32 "
        "{%0,%1,%2,%3}, {%4,%5,%6,%7}, {%8,%9}, {%0,%1,%2,%3};"
        : "+f"(d[0]), "+f"(d[1]), "+f"(d[2]), "+f"(d[3])
        : "r"(a[0]), "r"(a[1]), "r"(a[2]), "r"(a[3]), "r"(b[0]), "r"(b[1]));
}
__device__ __forceinline__ void cpasync16(uint32_t dst, const void* src) {
    asm volatile("cp.async.cg.shared.global [%0], [%1], 16;" :: "r"(dst), "l"(src));
}
#define CP_COMMIT() asm volatile("cp.async.commit_group;" ::: "memory")
#define CP_WAIT1()  asm volatile("cp.async.wait_group 1;" ::: "memory")
#define CP_WAIT0()  asm volatile("cp.async.wait_group 0;" ::: "memory")

// ---------------------------------------------------------------------------
// H/L split helpers (fp16)
// ---------------------------------------------------------------------------
__device__ __forceinline__ void splitHL(float v, fp16& h, fp16& l) {
    h = __float2half(v);
    l = __float2half(v - __half2float(h));
}
__device__ __forceinline__ void storeHL2(fp16* ph, fp16* pl, float v0, float v1) {
    fp16 h0, l0, h1, l1;
    splitHL(v0, h0, l0);
    splitHL(v1, h1, l1);
    *(half2*)ph = __halves2half2(h0, h1);
    *(half2*)pl = __halves2half2(l0, l1);
}
__device__ __forceinline__ void storeH2(fp16* ph, float v0, float v1) {
    *(half2*)ph = __halves2half2(__float2half(v0), __float2half(v1));
}

// ---------------------------------------------------------------------------
// Weight conversion: rows 0-511 Wq, 512-1023 Wk, 1024-1535 Wv, 1536-2047 Wo
// H for all rows; L used only for Wv/Wo (A-side) but written uniformly.
// ---------------------------------------------------------------------------
__global__ __launch_bounds__(256) void convert_w_kernel(
    const float* __restrict__ Wq, const float* __restrict__ Wk,
    const float* __restrict__ Wv, const float* __restrict__ Wo,
    fp16* __restrict__ WH, fp16* __restrict__ WL)
{
    int r = blockIdx.x;
    int tid = threadIdx.x;
    const float* src = (r < 512)  ? Wq + (size_t)r * 512
                     : (r < 1024) ? Wk + (size_t)(r-512) * 512
                     : (r < 1536) ? Wv + (size_t)(r-1024) * 512
                                  : Wo + (size_t)(r-1536) * 512;
    fp16* dh = WH + (size_t)r * 512;
    fp16* dl = WL + (size_t)r * 512;
    for (int k = tid; k < 512; k += 256) {
        fp16 h, l; splitHL(src[k], h, l);
        dh[k] = h; dl[k] = l;
    }
}

// ---------------------------------------------------------------------------
// GroupNorm + SiLU -> gn planes [b][n][512] (H + L; gn is A in QK, B-H in V)
// ---------------------------------------------------------------------------
__global__ __launch_bounds__(256) void gn_silu_kernel(
    const float* __restrict__ x, const float* __restrict__ gamma,
    const float* __restrict__ beta, fp16* __restrict__ gnH, fp16* __restrict__ gnL)
{
    int bg = blockIdx.x;
    int b = bg / GG, g = bg % GG;
    const float* xp = x + ((size_t)b*CC + g*CPG) * HW;
    int tid = threadIdx.x;

    float s = 0.f, ss = 0.f;
    for (int i = tid; i < CPG*HW; i += 256) {
        float v = xp[i];
        s += v; ss += v*v;
    }
    __shared__ float sh0[256], sh1[256];
    sh0[tid] = s; sh1[tid] = ss;
    __syncthreads();
    for (int o = 128; o > 0; o >>= 1) {
        if (tid < o) { sh0[tid] += sh0[tid+o]; sh1[tid] += sh1[tid+o]; }
        __syncthreads();
    }
    const float inv_n = 1.f / (float)(CPG*HW);
    float mean = sh0[0] * inv_n;
    float var  = sh1[0] * inv_n - mean*mean;
    float rstd = rsqrtf(var + EPSV);

    float gm[CPG], bt[CPG];
    #pragma unroll
    for (int cl = 0; cl < CPG; cl++) { gm[cl] = gamma[g*CPG+cl]; bt[cl] = beta[g*CPG+cl]; }

    for (int n = tid; n < HW; n += 256) {
        size_t off = ((size_t)b*HW + n) * 512 + g*CPG;
        fp16* dh = gnH + off;
        fp16* dl = gnL + off;
        #pragma unroll
        for (int cl = 0; cl < CPG; cl += 2) {
            float v0 = (xp[cl*HW + n]     - mean) * rstd * gm[cl]   + bt[cl];
            float v1 = (xp[(cl+1)*HW + n] - mean) * rstd * gm[cl+1] + bt[cl+1];
            v0 = v0 / (1.f + __expf(-v0));
            v1 = v1 / (1.f + __expf(-v1));
            storeHL2(dh + cl, dl + cl, v0, v1);
        }
    }
}

// ---------------------------------------------------------------------------
// Row softmax -> attn planes [b*i][1024] (H + L; attn is A in AV)
// ---------------------------------------------------------------------------
__global__ __launch_bounds__(256) void softmax_kernel(
    const float* __restrict__ s, fp16* __restrict__ aH, fp16* __restrict__ aL)
{
    const float* sp = s + (size_t)blockIdx.x * HW;
    size_t ro = (size_t)blockIdx.x * HW;
    int tid = threadIdx.x;
    float4 v = *(const float4*)(sp + tid*4);
    float m = fmaxf(fmaxf(v.x, v.y), fmaxf(v.z, v.w));

    __shared__ float sh[256];
    sh[tid] = m; __syncthreads();
    for (int o = 128; o > 0; o >>= 1) {
        if (tid < o) sh[tid] = fmaxf(sh[tid], sh[tid+o]);
        __syncthreads();
    }
    m = sh[0];
    __syncthreads();

    v.x = __expf(v.x - m); v.y = __expf(v.y - m);
    v.z = __expf(v.z - m); v.w = __expf(v.w - m);
    sh[tid] = v.x + v.y + v.z + v.w; __syncthreads();
    for (int o = 128; o > 0; o >>= 1) {
        if (tid < o) sh[tid] += sh[tid+o];
        __syncthreads();
    }
    float inv = 1.f / sh[0];
    storeHL2(aH + ro + tid*4,     aL + ro + tid*4,     v.x*inv, v.y*inv);
    storeHL2(aH + ro + tid*4 + 2, aL + ro + tid*4 + 2, v.z*inv, v.w*inv);
}

// ---------------------------------------------------------------------------
// HMMA GEMM over fp16 planes, 2-segment schedule:
//   seg0: A_H x B_H,  seg1: A_L x B_H     (A_H x B_L dropped, ~2^-12.5 rel)
// CTA tile 128x128, 4 warps (2x2), warp tile 64x64, K-chunk 64,
// 3-stage cp.async pipeline, XOR-swizzled smem.
// EPI: 0=QK  1=V  2=SCORES  3=AV  4=OUT
// ---------------------------------------------------------------------------
#define KC       64
#define OPB      16384                 // 128 rows * 128 B
#define STAGE_B  (2*OPB)               // 32 KB
#define SMEM_BYTES (3*STAGE_B)         // 96 KB

__device__ __forceinline__ void load_stage(uint32_t dst, const fp16* Ap, const fp16* Bp,
                                           int Kb, int tid)
{
    #pragma unroll
    for (int it = 0; it < 8; it++) {
        int e   = it*128 + tid;        // 0..1023
        int row = e >> 3, grp = e & 7;
        uint32_t off = (uint32_t)(row*128 + ((grp ^ (row & 7)) << 4));
        cpasync16(dst + off,       Ap + (size_t)row * Kb + grp*8);
        cpasync16(dst + OPB + off, Bp + (size_t)row * Kb + grp*8);
    }
}

template<int EPI>
__global__ __launch_bounds__(128, 2) void hmma_gemm(
    const fp16* __restrict__ AH, const fp16* __restrict__ AL, size_t aStr,
    const fp16* __restrict__ BH, size_t bStr, int Kb,
    const float* __restrict__ bias, const float* __restrict__ bias2,
    const float* __restrict__ xres,
    float* __restrict__ fOut, fp16* __restrict__ oH, fp16* __restrict__ oL,
    fp16* __restrict__ o2H, float scale)
{
    extern __shared__ char smem[];
    const uint32_t sbase = smem_u32(smem);
    const int tid  = threadIdx.x;
    const int lane = tid & 31, wid = tid >> 5;
    const int wm = wid >> 1, wn = wid & 1;
    const int bz = blockIdx.z;
    const int m0 = blockIdx.y * 128, n0 = blockIdx.x * 128;

    const fp16* AHb = AH + bz*aStr + (size_t)m0 * Kb;
    const fp16* ALb = AL + bz*aStr + (size_t)m0 * Kb;
    const fp16* BHb = BH + bz*bStr + (size_t)n0 * Kb;

    const int ncb = Kb >> 6;           // chunks per segment
    const int nch = 2 * ncb;

    // ldmatrix per-thread geometry
    const int aR0 = wm*64 + (lane & 15);
    const int aGs = lane >> 4;
    const int bR0 = wn*64 + (lane & 7) + ((lane >> 4) & 1) * 8;
    const int bGs = (lane >> 3) & 1;

    float acc[4][8][4];
    #pragma unroll
    for (int i = 0; i < 4; i++)
        #pragma unroll
        for (int j = 0; j < 8; j++)
            #pragma unroll
            for (int c = 0; c < 4; c++) acc[i][j][c] = 0.f;

    // prologue: chunks 0,1 (both in segment 0 since ncb>=8)
    load_stage(sbase,           AHb, BHb, Kb, tid);  CP_COMMIT();
    load_stage(sbase + STAGE_B, AHb + KC, BHb + KC, Kb, tid);  CP_COMMIT();

    int stage = 0;
    for (int t = 0; t < nch; t++) {
        if (t + 2 < nch) CP_WAIT1(); else CP_WAIT0();
        __syncthreads();
        if (t + 2 < nch) {
            int u = t + 2;
            int kk  = (u >= ncb) ? (u - ncb) * KC : u * KC;
            const fp16* Ap = ((u >= ncb) ? ALb : AHb) + kk;
            const fp16* Bp = BHb + kk;
            int s2 = stage + 2; if (s2 >= 3) s2 -= 3;
            load_stage(sbase + s2*STAGE_B, Ap, Bp, Kb, tid);
            CP_COMMIT();
        }

        const uint32_t abase = sbase + stage*STAGE_B;
        const uint32_t bbase = abase + OPB;

        #pragma unroll
        for (int ks8 = 0; ks8 < 8; ks8 += 2) {
            uint32_t afr[4][4];
            #pragma unroll
            for (int mf = 0; mf < 4; mf++) {
                int r = aR0 + mf*16;
                uint32_t g = (uint32_t)(ks8 + aGs);
                ldsm4(afr[mf], abase + (uint32_t)(r*128) + ((g ^ (uint32_t)(r & 7)) << 4));
            }
            uint32_t bfr[8][2];
            #pragma unroll
            for (int p = 0; p < 4; p++) {
                int r = bR0 + p*16;
                uint32_t g = (uint32_t)(ks8 + bGs);
                uint32_t rr[4];
                ldsm4(rr, bbase + (uint32_t)(r*128) + ((g ^ (uint32_t)(r & 7)) << 4));
                bfr[2*p][0]   = rr[0]; bfr[2*p][1]   = rr[1];
                bfr[2*p+1][0] = rr[2]; bfr[2*p+1][1] = rr[3];
            }
            #pragma unroll
            for (int mf = 0; mf < 4; mf++)
                #pragma unroll
                for (int nf = 0; nf < 8; nf++)
                    mma16816(acc[mf][nf], afr[mf], bfr[nf]);
        }

        stage++; if (stage == 3) stage = 0;
    }

    // ---------------- epilogue ----------------
    const int tr = lane >> 2;
    const int tc = (lane & 3) * 2;

    #pragma unroll
    for (int mf = 0; mf < 4; mf++) {
        #pragma unroll
        for (int half = 0; half < 2; half++) {
            int r = m0 + wm*64 + mf*16 + tr + half*8;
            #pragma unroll
            for (int nf = 0; nf < 8; nf++) {
                int c = n0 + wn*64 + nf*8 + tc;
                float d0 = acc[mf][nf][half*2 + 0];
                float d1 = acc[mf][nf][half*2 + 1];

                if (EPI == 0) {                 // QK: D[i][ch], ch<512 q else k
                    if (c < 512) {              // q: A-side in scores -> H+L
                        d0 += bias[c]; d1 += bias[c+1];
                        size_t idx = ((size_t)bz*HW + r) * 512 + c;
                        storeHL2(oH + idx, oL + idx, d0, d1);
                    } else {                    // k: B-side only -> H
                        d0 += bias2[c-512]; d1 += bias2[c-511];
                        size_t idx = ((size_t)bz*HW + r) * 512 + (c - 512);
                        storeH2(o2H + idx, d0, d1);
                    }
                } else if (EPI == 1) {          // V: D[ch][i], B-side only -> H
                    float bb = bias[r];
                    size_t idx = ((size_t)bz*CC + r) * HW + c;
                    storeH2(oH + idx, d0+bb, d1+bb);
                } else if (EPI == 2) {          // scores fp32 * scale
                    *(float2*)(fOut + ((size_t)bz*HW + r) * HW + c)
                        = make_float2(d0*scale, d1*scale);
                } else if (EPI == 3) {          // AV: D[i][ch], B-side only -> H
                    size_t idx = ((size_t)bz*HW + r) * 512 + c;
                    storeH2(oH + idx, d0, d1);
                } else {                        // OUT: + bias + residual
                    float bb = bias[r];
                    size_t off = ((size_t)bz*CC + r) * HW + c;
                    float2 xr = *(const float2*)(xres + off);
                    *(float2*)(fOut + off) = make_float2(d0+bb+xr.x, d1+bb+xr.y);
                }
            }
        }
    }
}

// ---------------------------------------------------------------------------
extern "C" void kernel_launch(void* const* d_in, const int* in_sizes, int n_in,
                              void* d_out, int out_size)
{
    const float* x     = (const float*)d_in[0];
    const float* Wq    = (const float*)d_in[1];
    const float* bq    = (const float*)d_in[2];
    const float* Wk    = (const float*)d_in[3];
    const float* bk    = (const float*)d_in[4];
    const float* Wv    = (const float*)d_in[5];
    const float* bv    = (const float*)d_in[6];
    const float* Wo    = (const float*)d_in[7];
    const float* bo    = (const float*)d_in[8];
    const float* gamma = (const float*)d_in[9];
    const float* beta  = (const float*)d_in[10];
    float* out = (float*)d_out;

    unsigned char* base = nullptr;
    cudaGetSymbolAddress((void**)&base, g_scratch);
    fp16*  WH  = (fp16*)(base + OFF_WH);
    fp16*  WL  = (fp16*)(base + OFF_WL);
    fp16*  gnH = (fp16*)(base + OFF_GNH);
    fp16*  gnL = (fp16*)(base + OFF_GNL);
    fp16*  qH  = (fp16*)(base + OFF_QH);
    fp16*  qL  = (fp16*)(base + OFF_QL);
    fp16*  kH  = (fp16*)(base + OFF_KH);
    fp16*  vH  = (fp16*)(base + OFF_VH);
    fp16*  aH  = (fp16*)(base + OFF_AH);
    fp16*  aL  = (fp16*)(base + OFF_AL);
    fp16*  hhH = (fp16*)(base + OFF_HHH);
    float* sS  = (float*)(base + OFF_S);

    cudaFuncSetAttribute(hmma_gemm<0>, cudaFuncAttributeMaxDynamicSharedMemorySize, SMEM_BYTES);
    cudaFuncSetAttribute(hmma_gemm<1>, cudaFuncAttributeMaxDynamicSharedMemorySize, SMEM_BYTES);
    cudaFuncSetAttribute(hmma_gemm<2>, cudaFuncAttributeMaxDynamicSharedMemorySize, SMEM_BYTES);
    cudaFuncSetAttribute(hmma_gemm<3>, cudaFuncAttributeMaxDynamicSharedMemorySize, SMEM_BYTES);
    cudaFuncSetAttribute(hmma_gemm<4>, cudaFuncAttributeMaxDynamicSharedMemorySize, SMEM_BYTES);

    const float scale = 1.0f / sqrtf((float)CC);

    convert_w_kernel<<<2048, 256>>>(Wq, Wk, Wv, Wo, WH, WL);
    gn_silu_kernel<<<BB*GG, 256>>>(x, gamma, beta, gnH, gnL);

    const size_t PXS = (size_t)HW * 512;   // pixel-row plane stride (per b)
    const size_t CHS = (size_t)CC * HW;    // channel-row plane stride (per b)

    // QK: M=1024 pixels (A=gn H+L), N=1024 q|k rows (B=W H), K=512
    hmma_gemm<0><<<dim3(8, 8, BB), 128, SMEM_BYTES>>>(
        gnH, gnL, PXS, WH, 0, 512, bq, bk, nullptr,
        nullptr, qH, qL, kH, 0.f);

    // V: M=512 channels (A=Wv H+L), N=1024 pixels (B=gn H), K=512
    hmma_gemm<1><<<dim3(8, 4, BB), 128, SMEM_BYTES>>>(
        WH + (size_t)1024*512, WL + (size_t)1024*512, 0, gnH, PXS, 512,
        bv, nullptr, nullptr, nullptr, vH, nullptr, nullptr, 0.f);

    // scores: M=1024 i (A=q H+L), N=1024 j (B=k H), K=512 -> fp32 * scale
    hmma_gemm<2><<<dim3(8, 8, BB), 128, SMEM_BYTES>>>(
        qH, qL, PXS, kH, PXS, 512, nullptr, nullptr, nullptr,
        sS, nullptr, nullptr, nullptr, scale);

    softmax_kernel<<<BB*HW, 256>>>(sS, aH, aL);

    // AV: M=1024 i (A=attn H+L), N=512 ch (B=v H), K=1024 -> hh H
    hmma_gemm<3><<<dim3(4, 8, BB), 128, SMEM_BYTES>>>(
        aH, aL, (size_t)HW*HW, vH, CHS, 1024, nullptr, nullptr, nullptr,
        nullptr, hhH, nullptr, nullptr, 0.f);

    // OUT: M=512 ch (A=Wo H+L), N=1024 i (B=hh H), K=512, +bo +x
    hmma_gemm<4><<<dim3(8, 4, BB), 128, SMEM_BYTES>>>(
        WH + (size_t)1536*512, WL + (size_t)1536*512, 0, hhH, PXS, 512,
        bo, nullptr, x, out, nullptr, nullptr, nullptr, 0.f);
}

// round 7
// speedup vs baseline: 7.5399x; 1.6544x over previous
#include <cuda_runtime.h>
#include <cuda_fp16.h>
#include <cstdint>
#include <math.h>

typedef __half fp16;

#define BB  16
#define CC  512
#define HW  1024
#define GG  32
#define CPG 16
#define EPSV 1e-5f

// ---------------------------------------------------------------------------
// Scratch: pure fp16 tensors (single plane each) + fp32 scores.
// ---------------------------------------------------------------------------
#define PL_W    ((size_t)2048*512)          // Wq|Wk|Wv|Wo rows x 512
#define PL_GN   ((size_t)BB*HW*512)
#define PL_Q    ((size_t)BB*HW*512)
#define PL_K    ((size_t)BB*HW*512)
#define PL_V    ((size_t)BB*CC*HW)          // [b][c][i]
#define PL_ATT  ((size_t)BB*HW*HW)          // [b][i][j]
#define PL_HH   ((size_t)BB*HW*512)         // [b][i][c]

#define OFF_WH   ((size_t)0)
#define OFF_GNH  (OFF_WH  + PL_W*2)
#define OFF_QH   (OFF_GNH + PL_GN*2)
#define OFF_KH   (OFF_QH  + PL_Q*2)
#define OFF_VH   (OFF_KH  + PL_K*2)
#define OFF_AH   (OFF_VH  + PL_V*2)
#define OFF_HHH  (OFF_AH  + PL_ATT*2)
#define OFF_S    (OFF_HHH + PL_HH*2)
#define SZ_S     ((size_t)BB*HW*HW*4)
#define SCRATCH_BYTES (OFF_S + SZ_S)

__device__ __align__(256) unsigned char g_scratch[SCRATCH_BYTES];

// ---------------------------------------------------------------------------
// PTX helpers
// ---------------------------------------------------------------------------
__device__ __forceinline__ uint32_t smem_u32(const void* p) {
    uint32_t a;
    asm("{ .reg .u64 t; cvta.to.shared.u64 t, %1; cvt.u32.u64 %0, t; }" : "=r"(a) : "l"(p));
    return a;
}
__device__ __forceinline__ void ldsm4(uint32_t* r, uint32_t addr) {
    asm volatile("ldmatrix.sync.aligned.m8n8.x4.shared.b16 {%0,%1,%2,%3}, [%4];"
                 : "=r"(r[0]), "=r"(r[1]), "=r"(r[2]), "=r"(r[3]) : "r"(addr));
}
__device__ __forceinline__ void mma16816(float* d, const uint32_t* a, const uint32_t* b) {
    asm volatile("mma.sync.aligned.m16n8k16.row.col.f32.f16.f16.f32 "
        "{%0,%1,%2,%3}, {%4,%5,%6,%7}, {%8,%9}, {%0,%1,%2,%3};"
        : "+f"(d[0]), "+f"(d[1]), "+f"(d[2]), "+f"(d[3])
        : "r"(a[0]), "r"(a[1]), "r"(a[2]), "r"(a[3]), "r"(b[0]), "r"(b[1]));
}
__device__ __forceinline__ void cpasync16(uint32_t dst, const void* src) {
    asm volatile("cp.async.cg.shared.global [%0], [%1], 16;" :: "r"(dst), "l"(src));
}
#define CP_COMMIT() asm volatile("cp.async.commit_group;" ::: "memory")
#define CP_WAIT1()  asm volatile("cp.async.wait_group 1;" ::: "memory")
#define CP_WAIT0()  asm volatile("cp.async.wait_group 0;" ::: "memory")

__device__ __forceinline__ void storeH2(fp16* ph, float v0, float v1) {
    *(half2*)ph = __halves2half2(__float2half(v0), __float2half(v1));
}

// ---------------------------------------------------------------------------
// Weight conversion: rows 0-511 Wq, 512-1023 Wk, 1024-1535 Wv, 1536-2047 Wo
// ---------------------------------------------------------------------------
__global__ __launch_bounds__(256) void convert_w_kernel(
    const float* __restrict__ Wq, const float* __restrict__ Wk,
    const float* __restrict__ Wv, const float* __restrict__ Wo,
    fp16* __restrict__ WH)
{
    int r = blockIdx.x;
    int tid = threadIdx.x;
    const float* src = (r < 512)  ? Wq + (size_t)r * 512
                     : (r < 1024) ? Wk + (size_t)(r-512) * 512
                     : (r < 1536) ? Wv + (size_t)(r-1024) * 512
                                  : Wo + (size_t)(r-1536) * 512;
    fp16* dh = WH + (size_t)r * 512;
    for (int k = tid; k < 512; k += 256) dh[k] = __float2half(src[k]);
}

// ---------------------------------------------------------------------------
// GroupNorm + SiLU -> gn plane [b][n][512]
// ---------------------------------------------------------------------------
__global__ __launch_bounds__(256) void gn_silu_kernel(
    const float* __restrict__ x, const float* __restrict__ gamma,
    const float* __restrict__ beta, fp16* __restrict__ gnH)
{
    int bg = blockIdx.x;
    int b = bg / GG, g = bg % GG;
    const float* xp = x + ((size_t)b*CC + g*CPG) * HW;
    int tid = threadIdx.x;

    float s = 0.f, ss = 0.f;
    for (int i = tid; i < CPG*HW; i += 256) {
        float v = xp[i];
        s += v; ss += v*v;
    }
    __shared__ float sh0[256], sh1[256];
    sh0[tid] = s; sh1[tid] = ss;
    __syncthreads();
    for (int o = 128; o > 0; o >>= 1) {
        if (tid < o) { sh0[tid] += sh0[tid+o]; sh1[tid] += sh1[tid+o]; }
        __syncthreads();
    }
    const float inv_n = 1.f / (float)(CPG*HW);
    float mean = sh0[0] * inv_n;
    float var  = sh1[0] * inv_n - mean*mean;
    float rstd = rsqrtf(var + EPSV);

    float gm[CPG], bt[CPG];
    #pragma unroll
    for (int cl = 0; cl < CPG; cl++) { gm[cl] = gamma[g*CPG+cl]; bt[cl] = beta[g*CPG+cl]; }

    for (int n = tid; n < HW; n += 256) {
        fp16* dh = gnH + ((size_t)b*HW + n) * 512 + g*CPG;
        #pragma unroll
        for (int cl = 0; cl < CPG; cl += 2) {
            float v0 = (xp[cl*HW + n]     - mean) * rstd * gm[cl]   + bt[cl];
            float v1 = (xp[(cl+1)*HW + n] - mean) * rstd * gm[cl+1] + bt[cl+1];
            v0 = v0 / (1.f + __expf(-v0));
            v1 = v1 / (1.f + __expf(-v1));
            storeH2(dh + cl, v0, v1);
        }
    }
}

// ---------------------------------------------------------------------------
// Row softmax -> attn plane [b*i][1024]
// ---------------------------------------------------------------------------
__global__ __launch_bounds__(256) void softmax_kernel(
    const float* __restrict__ s, fp16* __restrict__ aH)
{
    const float* sp = s + (size_t)blockIdx.x * HW;
    size_t ro = (size_t)blockIdx.x * HW;
    int tid = threadIdx.x;
    float4 v = *(const float4*)(sp + tid*4);
    float m = fmaxf(fmaxf(v.x, v.y), fmaxf(v.z, v.w));

    __shared__ float sh[256];
    sh[tid] = m; __syncthreads();
    for (int o = 128; o > 0; o >>= 1) {
        if (tid < o) sh[tid] = fmaxf(sh[tid], sh[tid+o]);
        __syncthreads();
    }
    m = sh[0];
    __syncthreads();

    v.x = __expf(v.x - m); v.y = __expf(v.y - m);
    v.z = __expf(v.z - m); v.w = __expf(v.w - m);
    sh[tid] = v.x + v.y + v.z + v.w; __syncthreads();
    for (int o = 128; o > 0; o >>= 1) {
        if (tid < o) sh[tid] += sh[tid+o];
        __syncthreads();
    }
    float inv = 1.f / sh[0];
    storeH2(aH + ro + tid*4,     v.x*inv, v.y*inv);
    storeH2(aH + ro + tid*4 + 2, v.z*inv, v.w*inv);
}

// ---------------------------------------------------------------------------
// HMMA GEMM, pure fp16 single segment.
// CTA tile 128x128, 4 warps (2x2), warp tile 64x64, K-chunk 64,
// 3-stage cp.async pipeline, XOR-swizzled smem.
// EPI: 0=QK  1=V  2=SCORES  3=AV  4=OUT
// ---------------------------------------------------------------------------
#define KC       64
#define OPB      16384                 // 128 rows * 128 B
#define STAGE_B  (2*OPB)               // 32 KB
#define SMEM_BYTES (3*STAGE_B)         // 96 KB

__device__ __forceinline__ void load_stage(uint32_t dst, const fp16* Ap, const fp16* Bp,
                                           int Kb, int tid)
{
    #pragma unroll
    for (int it = 0; it < 8; it++) {
        int e   = it*128 + tid;        // 0..1023
        int row = e >> 3, grp = e & 7;
        uint32_t off = (uint32_t)(row*128 + ((grp ^ (row & 7)) << 4));
        cpasync16(dst + off,       Ap + (size_t)row * Kb + grp*8);
        cpasync16(dst + OPB + off, Bp + (size_t)row * Kb + grp*8);
    }
}

template<int EPI>
__global__ __launch_bounds__(128, 2) void hmma_gemm(
    const fp16* __restrict__ AH, size_t aStr,
    const fp16* __restrict__ BH, size_t bStr, int Kb,
    const float* __restrict__ bias, const float* __restrict__ bias2,
    const float* __restrict__ xres,
    float* __restrict__ fOut, fp16* __restrict__ oH, fp16* __restrict__ o2H,
    float scale)
{
    extern __shared__ char smem[];
    const uint32_t sbase = smem_u32(smem);
    const int tid  = threadIdx.x;
    const int lane = tid & 31, wid = tid >> 5;
    const int wm = wid >> 1, wn = wid & 1;
    const int bz = blockIdx.z;
    const int m0 = blockIdx.y * 128, n0 = blockIdx.x * 128;

    const fp16* AHb = AH + bz*aStr + (size_t)m0 * Kb;
    const fp16* BHb = BH + bz*bStr + (size_t)n0 * Kb;

    const int nch = Kb >> 6;

    // ldmatrix per-thread geometry
    const int aR0 = wm*64 + (lane & 15);
    const int aGs = lane >> 4;
    const int bR0 = wn*64 + (lane & 7) + ((lane >> 4) & 1) * 8;
    const int bGs = (lane >> 3) & 1;

    float acc[4][8][4];
    #pragma unroll
    for (int i = 0; i < 4; i++)
        #pragma unroll
        for (int j = 0; j < 8; j++)
            #pragma unroll
            for (int c = 0; c < 4; c++) acc[i][j][c] = 0.f;

    // prologue: chunks 0,1
    load_stage(sbase,           AHb,      BHb,      Kb, tid);  CP_COMMIT();
    load_stage(sbase + STAGE_B, AHb + KC, BHb + KC, Kb, tid);  CP_COMMIT();

    int stage = 0;
    for (int t = 0; t < nch; t++) {
        if (t + 2 < nch) CP_WAIT1(); else CP_WAIT0();
        __syncthreads();
        if (t + 2 < nch) {
            int kk = (t + 2) * KC;
            int s2 = stage + 2; if (s2 >= 3) s2 -= 3;
            load_stage(sbase + s2*STAGE_B, AHb + kk, BHb + kk, Kb, tid);
            CP_COMMIT();
        }

        const uint32_t abase = sbase + stage*STAGE_B;
        const uint32_t bbase = abase + OPB;

        #pragma unroll
        for (int ks8 = 0; ks8 < 8; ks8 += 2) {
            uint32_t afr[4][4];
            #pragma unroll
            for (int mf = 0; mf < 4; mf++) {
                int r = aR0 + mf*16;
                uint32_t g = (uint32_t)(ks8 + aGs);
                ldsm4(afr[mf], abase + (uint32_t)(r*128) + ((g ^ (uint32_t)(r & 7)) << 4));
            }
            uint32_t bfr[8][2];
            #pragma unroll
            for (int p = 0; p < 4; p++) {
                int r = bR0 + p*16;
                uint32_t g = (uint32_t)(ks8 + bGs);
                uint32_t rr[4];
                ldsm4(rr, bbase + (uint32_t)(r*128) + ((g ^ (uint32_t)(r & 7)) << 4));
                bfr[2*p][0]   = rr[0]; bfr[2*p][1]   = rr[1];
                bfr[2*p+1][0] = rr[2]; bfr[2*p+1][1] = rr[3];
            }
            #pragma unroll
            for (int mf = 0; mf < 4; mf++)
                #pragma unroll
                for (int nf = 0; nf < 8; nf++)
                    mma16816(acc[mf][nf], afr[mf], bfr[nf]);
        }

        stage++; if (stage == 3) stage = 0;
    }

    // ---------------- epilogue ----------------
    const int tr = lane >> 2;
    const int tc = (lane & 3) * 2;

    #pragma unroll
    for (int mf = 0; mf < 4; mf++) {
        #pragma unroll
        for (int half = 0; half < 2; half++) {
            int r = m0 + wm*64 + mf*16 + tr + half*8;
            #pragma unroll
            for (int nf = 0; nf < 8; nf++) {
                int c = n0 + wn*64 + nf*8 + tc;
                float d0 = acc[mf][nf][half*2 + 0];
                float d1 = acc[mf][nf][half*2 + 1];

                if (EPI == 0) {                 // QK: D[i][ch], ch<512 q else k
                    if (c < 512) {
                        d0 += bias[c]; d1 += bias[c+1];
                        size_t idx = ((size_t)bz*HW + r) * 512 + c;
                        storeH2(oH + idx, d0, d1);
                    } else {
                        d0 += bias2[c-512]; d1 += bias2[c-511];
                        size_t idx = ((size_t)bz*HW + r) * 512 + (c - 512);
                        storeH2(o2H + idx, d0, d1);
                    }
                } else if (EPI == 1) {          // V: D[ch][i]
                    float bb = bias[r];
                    size_t idx = ((size_t)bz*CC + r) * HW + c;
                    storeH2(oH + idx, d0+bb, d1+bb);
                } else if (EPI == 2) {          // scores fp32 * scale
                    *(float2*)(fOut + ((size_t)bz*HW + r) * HW + c)
                        = make_float2(d0*scale, d1*scale);
                } else if (EPI == 3) {          // AV: D[i][ch]
                    size_t idx = ((size_t)bz*HW + r) * 512 + c;
                    storeH2(oH + idx, d0, d1);
                } else {                        // OUT: + bias + residual
                    float bb = bias[r];
                    size_t off = ((size_t)bz*CC + r) * HW + c;
                    float2 xr = *(const float2*)(xres + off);
                    *(float2*)(fOut + off) = make_float2(d0+bb+xr.x, d1+bb+xr.y);
                }
            }
        }
    }
}

// ---------------------------------------------------------------------------
extern "C" void kernel_launch(void* const* d_in, const int* in_sizes, int n_in,
                              void* d_out, int out_size)
{
    const float* x     = (const float*)d_in[0];
    const float* Wq    = (const float*)d_in[1];
    const float* bq    = (const float*)d_in[2];
    const float* Wk    = (const float*)d_in[3];
    const float* bk    = (const float*)d_in[4];
    const float* Wv    = (const float*)d_in[5];
    const float* bv    = (const float*)d_in[6];
    const float* Wo    = (const float*)d_in[7];
    const float* bo    = (const float*)d_in[8];
    const float* gamma = (const float*)d_in[9];
    const float* beta  = (const float*)d_in[10];
    float* out = (float*)d_out;

    unsigned char* base = nullptr;
    cudaGetSymbolAddress((void**)&base, g_scratch);
    fp16*  WH  = (fp16*)(base + OFF_WH);
    fp16*  gnH = (fp16*)(base + OFF_GNH);
    fp16*  qH  = (fp16*)(base + OFF_QH);
    fp16*  kH  = (fp16*)(base + OFF_KH);
    fp16*  vH  = (fp16*)(base + OFF_VH);
    fp16*  aH  = (fp16*)(base + OFF_AH);
    fp16*  hhH = (fp16*)(base + OFF_HHH);
    float* sS  = (float*)(base + OFF_S);

    cudaFuncSetAttribute(hmma_gemm<0>, cudaFuncAttributeMaxDynamicSharedMemorySize, SMEM_BYTES);
    cudaFuncSetAttribute(hmma_gemm<1>, cudaFuncAttributeMaxDynamicSharedMemorySize, SMEM_BYTES);
    cudaFuncSetAttribute(hmma_gemm<2>, cudaFuncAttributeMaxDynamicSharedMemorySize, SMEM_BYTES);
    cudaFuncSetAttribute(hmma_gemm<3>, cudaFuncAttributeMaxDynamicSharedMemorySize, SMEM_BYTES);
    cudaFuncSetAttribute(hmma_gemm<4>, cudaFuncAttributeMaxDynamicSharedMemorySize, SMEM_BYTES);

    const float scale = 1.0f / sqrtf((float)CC);

    convert_w_kernel<<<2048, 256>>>(Wq, Wk, Wv, Wo, WH);
    gn_silu_kernel<<<BB*GG, 256>>>(x, gamma, beta, gnH);

    const size_t PXS = (size_t)HW * 512;   // pixel-row plane stride (per b)
    const size_t CHS = (size_t)CC * HW;    // channel-row plane stride (per b)

    // QK: M=1024 pixels (A=gn), N=1024 q|k rows (B=W), K=512
    hmma_gemm<0><<<dim3(8, 8, BB), 128, SMEM_BYTES>>>(
        gnH, PXS, WH, 0, 512, bq, bk, nullptr, nullptr, qH, kH, 0.f);

    // V: M=512 channels (A=Wv), N=1024 pixels (B=gn), K=512
    hmma_gemm<1><<<dim3(8, 4, BB), 128, SMEM_BYTES>>>(
        WH + (size_t)1024*512, 0, gnH, PXS, 512,
        bv, nullptr, nullptr, nullptr, vH, nullptr, 0.f);

    // scores: M=1024 i (A=q), N=1024 j (B=k), K=512 -> fp32 * scale
    hmma_gemm<2><<<dim3(8, 8, BB), 128, SMEM_BYTES>>>(
        qH, PXS, kH, PXS, 512, nullptr, nullptr, nullptr,
        sS, nullptr, nullptr, scale);

    softmax_kernel<<<BB*HW, 256>>>(sS, aH);

    // AV: M=1024 i (A=attn), N=512 ch (B=v), K=1024 -> hh
    hmma_gemm<3><<<dim3(4, 8, BB), 128, SMEM_BYTES>>>(
        aH, (size_t)HW*HW, vH, CHS, 1024, nullptr, nullptr, nullptr,
        nullptr, hhH, nullptr, 0.f);

    // OUT: M=512 ch (A=Wo), N=1024 i (B=hh), K=512, +bo +x
    hmma_gemm<4><<<dim3(8, 4, BB), 128, SMEM_BYTES>>>(
        WH + (size_t)1536*512, 0, hhH, PXS, 512,
        bo, nullptr, x, out, nullptr, nullptr, 0.f);
}

// round 8
// speedup vs baseline: 7.8586x; 1.0423x over previous
#include <cuda_runtime.h>
#include <cuda_fp16.h>
#include <cstdint>
#include <math.h>

typedef __half fp16;

#define BB  16
#define CC  512
#define HW  1024
#define GG  32
#define CPG 16
#define EPSV 1e-5f

// ---------------------------------------------------------------------------
// Scratch: pure fp16 tensors (single plane each) + fp32 scores.
// ---------------------------------------------------------------------------
#define PL_W    ((size_t)2048*512)          // Wq|Wk|Wv|Wo rows x 512
#define PL_GN   ((size_t)BB*HW*512)
#define PL_Q    ((size_t)BB*HW*512)
#define PL_K    ((size_t)BB*HW*512)
#define PL_V    ((size_t)BB*CC*HW)          // [b][c][i]
#define PL_ATT  ((size_t)BB*HW*HW)          // [b][i][j]
#define PL_HH   ((size_t)BB*HW*512)         // [b][i][c]

#define OFF_WH   ((size_t)0)
#define OFF_GNH  (OFF_WH  + PL_W*2)
#define OFF_QH   (OFF_GNH + PL_GN*2)
#define OFF_KH   (OFF_QH  + PL_Q*2)
#define OFF_VH   (OFF_KH  + PL_K*2)
#define OFF_AH   (OFF_VH  + PL_V*2)
#define OFF_HHH  (OFF_AH  + PL_ATT*2)
#define OFF_S    (OFF_HHH + PL_HH*2)
#define SZ_S     ((size_t)BB*HW*HW*4)
#define SCRATCH_BYTES (OFF_S + SZ_S)

__device__ __align__(256) unsigned char g_scratch[SCRATCH_BYTES];

// ---------------------------------------------------------------------------
// PTX helpers
// ---------------------------------------------------------------------------
__device__ __forceinline__ uint32_t smem_u32(const void* p) {
    uint32_t a;
    asm("{ .reg .u64 t; cvta.to.shared.u64 t, %1; cvt.u32.u64 %0, t; }" : "=r"(a) : "l"(p));
    return a;
}
__device__ __forceinline__ void ldsm4(uint32_t* r, uint32_t addr) {
    asm volatile("ldmatrix.sync.aligned.m8n8.x4.shared.b16 {%0,%1,%2,%3}, [%4];"
                 : "=r"(r[0]), "=r"(r[1]), "=r"(r[2]), "=r"(r[3]) : "r"(addr));
}
__device__ __forceinline__ void mma16816(float* d, const uint32_t* a, const uint32_t* b) {
    asm volatile("mma.sync.aligned.m16n8k16.row.col.f32.f16.f16.f32 "
        "{%0,%1,%2,%3}, {%4,%5,%6,%7}, {%8,%9}, {%0,%1,%2,%3};"
        : "+f"(d[0]), "+f"(d[1]), "+f"(d[2]), "+f"(d[3])
        : "r"(a[0]), "r"(a[1]), "r"(a[2]), "r"(a[3]), "r"(b[0]), "r"(b[1]));
}
__device__ __forceinline__ void cpasync16(uint32_t dst, const void* src) {
    asm volatile("cp.async.cg.shared.global [%0], [%1], 16;" :: "r"(dst), "l"(src));
}
#define CP_COMMIT() asm volatile("cp.async.commit_group;" ::: "memory")
#define CP_WAIT1()  asm volatile("cp.async.wait_group 1;" ::: "memory")
#define CP_WAIT0()  asm volatile("cp.async.wait_group 0;" ::: "memory")

__device__ __forceinline__ void storeH2(fp16* ph, float v0, float v1) {
    *(half2*)ph = __halves2half2(__float2half(v0), __float2half(v1));
}

// ---------------------------------------------------------------------------
// Weight conversion: rows 0-511 Wq, 512-1023 Wk, 1024-1535 Wv, 1536-2047 Wo
// ---------------------------------------------------------------------------
__global__ __launch_bounds__(256) void convert_w_kernel(
    const float* __restrict__ Wq, const float* __restrict__ Wk,
    const float* __restrict__ Wv, const float* __restrict__ Wo,
    fp16* __restrict__ WH)
{
    int r = blockIdx.x;
    int tid = threadIdx.x;
    const float* src = (r < 512)  ? Wq + (size_t)r * 512
                     : (r < 1024) ? Wk + (size_t)(r-512) * 512
                     : (r < 1536) ? Wv + (size_t)(r-1024) * 512
                                  : Wo + (size_t)(r-1536) * 512;
    fp16* dh = WH + (size_t)r * 512;
    for (int k = tid; k < 512; k += 256) dh[k] = __float2half(src[k]);
}

// ---------------------------------------------------------------------------
// GroupNorm + SiLU -> gn plane [b][n][512]
// ---------------------------------------------------------------------------
__global__ __launch_bounds__(256) void gn_silu_kernel(
    const float* __restrict__ x, const float* __restrict__ gamma,
    const float* __restrict__ beta, fp16* __restrict__ gnH)
{
    int bg = blockIdx.x;
    int b = bg / GG, g = bg % GG;
    const float* xp = x + ((size_t)b*CC + g*CPG) * HW;
    int tid = threadIdx.x;

    float s = 0.f, ss = 0.f;
    for (int i = tid; i < CPG*HW; i += 256) {
        float v = xp[i];
        s += v; ss += v*v;
    }
    __shared__ float sh0[256], sh1[256];
    sh0[tid] = s; sh1[tid] = ss;
    __syncthreads();
    for (int o = 128; o > 0; o >>= 1) {
        if (tid < o) { sh0[tid] += sh0[tid+o]; sh1[tid] += sh1[tid+o]; }
        __syncthreads();
    }
    const float inv_n = 1.f / (float)(CPG*HW);
    float mean = sh0[0] * inv_n;
    float var  = sh1[0] * inv_n - mean*mean;
    float rstd = rsqrtf(var + EPSV);

    float gm[CPG], bt[CPG];
    #pragma unroll
    for (int cl = 0; cl < CPG; cl++) { gm[cl] = gamma[g*CPG+cl]; bt[cl] = beta[g*CPG+cl]; }

    for (int n = tid; n < HW; n += 256) {
        fp16* dh = gnH + ((size_t)b*HW + n) * 512 + g*CPG;
        #pragma unroll
        for (int cl = 0; cl < CPG; cl += 2) {
            float v0 = (xp[cl*HW + n]     - mean) * rstd * gm[cl]   + bt[cl];
            float v1 = (xp[(cl+1)*HW + n] - mean) * rstd * gm[cl+1] + bt[cl+1];
            v0 = v0 / (1.f + __expf(-v0));
            v1 = v1 / (1.f + __expf(-v1));
            storeH2(dh + cl, v0, v1);
        }
    }
}

// ---------------------------------------------------------------------------
// Row softmax -> attn plane [b*i][1024]
// ---------------------------------------------------------------------------
__global__ __launch_bounds__(256) void softmax_kernel(
    const float* __restrict__ s, fp16* __restrict__ aH)
{
    const float* sp = s + (size_t)blockIdx.x * HW;
    size_t ro = (size_t)blockIdx.x * HW;
    int tid = threadIdx.x;
    float4 v = *(const float4*)(sp + tid*4);
    float m = fmaxf(fmaxf(v.x, v.y), fmaxf(v.z, v.w));

    __shared__ float sh[256];
    sh[tid] = m; __syncthreads();
    for (int o = 128; o > 0; o >>= 1) {
        if (tid < o) sh[tid] = fmaxf(sh[tid], sh[tid+o]);
        __syncthreads();
    }
    m = sh[0];
    __syncthreads();

    v.x = __expf(v.x - m); v.y = __expf(v.y - m);
    v.z = __expf(v.z - m); v.w = __expf(v.w - m);
    sh[tid] = v.x + v.y + v.z + v.w; __syncthreads();
    for (int o = 128; o > 0; o >>= 1) {
        if (tid < o) sh[tid] += sh[tid+o];
        __syncthreads();
    }
    float inv = 1.f / sh[0];
    storeH2(aH + ro + tid*4,     v.x*inv, v.y*inv);
    storeH2(aH + ro + tid*4 + 2, v.z*inv, v.w*inv);
}

// ---------------------------------------------------------------------------
// HMMA GEMM, pure fp16. CTA tile 128x128, 8 warps (2m x 4n), warp tile 64x32,
// 256 threads, <=128 regs (2 CTAs/SM = 16 warps/SM), K-chunk 64,
// 3-stage cp.async pipeline, XOR-swizzled smem.
// EPI: 0=QK  1=V  2=SCORES  3=AV  4=OUT
// ---------------------------------------------------------------------------
#define KC       64
#define OPB      16384                 // 128 rows * 128 B
#define STAGE_B  (2*OPB)               // 32 KB
#define SMEM_BYTES (3*STAGE_B)         // 96 KB

__device__ __forceinline__ void load_stage(uint32_t dst, const fp16* Ap, const fp16* Bp,
                                           int Kb, int tid)
{
    #pragma unroll
    for (int it = 0; it < 4; it++) {
        int e   = it*256 + tid;        // 0..1023
        int row = e >> 3, grp = e & 7;
        uint32_t off = (uint32_t)(row*128 + ((grp ^ (row & 7)) << 4));
        cpasync16(dst + off,       Ap + (size_t)row * Kb + grp*8);
        cpasync16(dst + OPB + off, Bp + (size_t)row * Kb + grp*8);
    }
}

template<int EPI>
__global__ __launch_bounds__(256, 2) void hmma_gemm(
    const fp16* __restrict__ AH, size_t aStr,
    const fp16* __restrict__ BH, size_t bStr, int Kb,
    const float* __restrict__ bias, const float* __restrict__ bias2,
    const float* __restrict__ xres,
    float* __restrict__ fOut, fp16* __restrict__ oH, fp16* __restrict__ o2H,
    float scale)
{
    extern __shared__ char smem[];
    const uint32_t sbase = smem_u32(smem);
    const int tid  = threadIdx.x;
    const int lane = tid & 31, wid = tid >> 5;
    const int wm = wid >> 2, wn = wid & 3;       // 2m x 4n warps
    const int bz = blockIdx.z;
    const int m0 = blockIdx.y * 128, n0 = blockIdx.x * 128;

    const fp16* AHb = AH + bz*aStr + (size_t)m0 * Kb;
    const fp16* BHb = BH + bz*bStr + (size_t)n0 * Kb;

    const int nch = Kb >> 6;

    // ldmatrix per-thread geometry
    const int aR0 = wm*64 + (lane & 15);
    const int aGs = lane >> 4;
    const int bR0 = wn*32 + (lane & 7) + ((lane >> 4) & 1) * 8;
    const int bGs = (lane >> 3) & 1;

    float acc[4][4][4];
    #pragma unroll
    for (int i = 0; i < 4; i++)
        #pragma unroll
        for (int j = 0; j < 4; j++)
            #pragma unroll
            for (int c = 0; c < 4; c++) acc[i][j][c] = 0.f;

    // prologue: chunks 0,1
    load_stage(sbase,           AHb,      BHb,      Kb, tid);  CP_COMMIT();
    load_stage(sbase + STAGE_B, AHb + KC, BHb + KC, Kb, tid);  CP_COMMIT();

    int stage = 0;
    for (int t = 0; t < nch; t++) {
        if (t + 2 < nch) CP_WAIT1(); else CP_WAIT0();
        __syncthreads();
        if (t + 2 < nch) {
            int kk = (t + 2) * KC;
            int s2 = stage + 2; if (s2 >= 3) s2 -= 3;
            load_stage(sbase + s2*STAGE_B, AHb + kk, BHb + kk, Kb, tid);
            CP_COMMIT();
        }

        const uint32_t abase = sbase + stage*STAGE_B;
        const uint32_t bbase = abase + OPB;

        #pragma unroll
        for (int ks8 = 0; ks8 < 8; ks8 += 2) {
            uint32_t afr[4][4];
            #pragma unroll
            for (int mf = 0; mf < 4; mf++) {
                int r = aR0 + mf*16;
                uint32_t g = (uint32_t)(ks8 + aGs);
                ldsm4(afr[mf], abase + (uint32_t)(r*128) + ((g ^ (uint32_t)(r & 7)) << 4));
            }
            uint32_t bfr[4][2];
            #pragma unroll
            for (int p = 0; p < 2; p++) {
                int r = bR0 + p*16;
                uint32_t g = (uint32_t)(ks8 + bGs);
                uint32_t rr[4];
                ldsm4(rr, bbase + (uint32_t)(r*128) + ((g ^ (uint32_t)(r & 7)) << 4));
                bfr[2*p][0]   = rr[0]; bfr[2*p][1]   = rr[1];
                bfr[2*p+1][0] = rr[2]; bfr[2*p+1][1] = rr[3];
            }
            #pragma unroll
            for (int mf = 0; mf < 4; mf++)
                #pragma unroll
                for (int nf = 0; nf < 4; nf++)
                    mma16816(acc[mf][nf], afr[mf], bfr[nf]);
        }

        stage++; if (stage == 3) stage = 0;
    }

    // ---------------- epilogue ----------------
    const int tr = lane >> 2;
    const int tc = (lane & 3) * 2;

    #pragma unroll
    for (int mf = 0; mf < 4; mf++) {
        #pragma unroll
        for (int half = 0; half < 2; half++) {
            int r = m0 + wm*64 + mf*16 + tr + half*8;
            #pragma unroll
            for (int nf = 0; nf < 4; nf++) {
                int c = n0 + wn*32 + nf*8 + tc;
                float d0 = acc[mf][nf][half*2 + 0];
                float d1 = acc[mf][nf][half*2 + 1];

                if (EPI == 0) {                 // QK: D[i][ch], ch<512 q else k
                    if (c < 512) {
                        d0 += bias[c]; d1 += bias[c+1];
                        size_t idx = ((size_t)bz*HW + r) * 512 + c;
                        storeH2(oH + idx, d0, d1);
                    } else {
                        d0 += bias2[c-512]; d1 += bias2[c-511];
                        size_t idx = ((size_t)bz*HW + r) * 512 + (c - 512);
                        storeH2(o2H + idx, d0, d1);
                    }
                } else if (EPI == 1) {          // V: D[ch][i]
                    float bb = bias[r];
                    size_t idx = ((size_t)bz*CC + r) * HW + c;
                    storeH2(oH + idx, d0+bb, d1+bb);
                } else if (EPI == 2) {          // scores fp32 * scale
                    *(float2*)(fOut + ((size_t)bz*HW + r) * HW + c)
                        = make_float2(d0*scale, d1*scale);
                } else if (EPI == 3) {          // AV: D[i][ch]
                    size_t idx = ((size_t)bz*HW + r) * 512 + c;
                    storeH2(oH + idx, d0, d1);
                } else {                        // OUT: + bias + residual
                    float bb = bias[r];
                    size_t off = ((size_t)bz*CC + r) * HW + c;
                    float2 xr = *(const float2*)(xres + off);
                    *(float2*)(fOut + off) = make_float2(d0+bb+xr.x, d1+bb+xr.y);
                }
            }
        }
    }
}

// ---------------------------------------------------------------------------
extern "C" void kernel_launch(void* const* d_in, const int* in_sizes, int n_in,
                              void* d_out, int out_size)
{
    const float* x     = (const float*)d_in[0];
    const float* Wq    = (const float*)d_in[1];
    const float* bq    = (const float*)d_in[2];
    const float* Wk    = (const float*)d_in[3];
    const float* bk    = (const float*)d_in[4];
    const float* Wv    = (const float*)d_in[5];
    const float* bv    = (const float*)d_in[6];
    const float* Wo    = (const float*)d_in[7];
    const float* bo    = (const float*)d_in[8];
    const float* gamma = (const float*)d_in[9];
    const float* beta  = (const float*)d_in[10];
    float* out = (float*)d_out;

    unsigned char* base = nullptr;
    cudaGetSymbolAddress((void**)&base, g_scratch);
    fp16*  WH  = (fp16*)(base + OFF_WH);
    fp16*  gnH = (fp16*)(base + OFF_GNH);
    fp16*  qH  = (fp16*)(base + OFF_QH);
    fp16*  kH  = (fp16*)(base + OFF_KH);
    fp16*  vH  = (fp16*)(base + OFF_VH);
    fp16*  aH  = (fp16*)(base + OFF_AH);
    fp16*  hhH = (fp16*)(base + OFF_HHH);
    float* sS  = (float*)(base + OFF_S);

    cudaFuncSetAttribute(hmma_gemm<0>, cudaFuncAttributeMaxDynamicSharedMemorySize, SMEM_BYTES);
    cudaFuncSetAttribute(hmma_gemm<1>, cudaFuncAttributeMaxDynamicSharedMemorySize, SMEM_BYTES);
    cudaFuncSetAttribute(hmma_gemm<2>, cudaFuncAttributeMaxDynamicSharedMemorySize, SMEM_BYTES);
    cudaFuncSetAttribute(hmma_gemm<3>, cudaFuncAttributeMaxDynamicSharedMemorySize, SMEM_BYTES);
    cudaFuncSetAttribute(hmma_gemm<4>, cudaFuncAttributeMaxDynamicSharedMemorySize, SMEM_BYTES);

    const float scale = 1.0f / sqrtf((float)CC);

    convert_w_kernel<<<2048, 256>>>(Wq, Wk, Wv, Wo, WH);
    gn_silu_kernel<<<BB*GG, 256>>>(x, gamma, beta, gnH);

    const size_t PXS = (size_t)HW * 512;   // pixel-row plane stride (per b)
    const size_t CHS = (size_t)CC * HW;    // channel-row plane stride (per b)

    // QK: M=1024 pixels (A=gn), N=1024 q|k rows (B=W), K=512
    hmma_gemm<0><<<dim3(8, 8, BB), 256, SMEM_BYTES>>>(
        gnH, PXS, WH, 0, 512, bq, bk, nullptr, nullptr, qH, kH, 0.f);

    // V: M=512 channels (A=Wv), N=1024 pixels (B=gn), K=512
    hmma_gemm<1><<<dim3(8, 4, BB), 256, SMEM_BYTES>>>(
        WH + (size_t)1024*512, 0, gnH, PXS, 512,
        bv, nullptr, nullptr, nullptr, vH, nullptr, 0.f);

    // scores: M=1024 i (A=q), N=1024 j (B=k), K=512 -> fp32 * scale
    hmma_gemm<2><<<dim3(8, 8, BB), 256, SMEM_BYTES>>>(
        qH, PXS, kH, PXS, 512, nullptr, nullptr, nullptr,
        sS, nullptr, nullptr, scale);

    softmax_kernel<<<BB*HW, 256>>>(sS, aH);

    // AV: M=1024 i (A=attn), N=512 ch (B=v), K=1024 -> hh
    hmma_gemm<3><<<dim3(4, 8, BB), 256, SMEM_BYTES>>>(
        aH, (size_t)HW*HW, vH, CHS, 1024, nullptr, nullptr, nullptr,
        nullptr, hhH, nullptr, 0.f);

    // OUT: M=512 ch (A=Wo), N=1024 i (B=hh), K=512, +bo +x
    hmma_gemm<4><<<dim3(8, 4, BB), 256, SMEM_BYTES>>>(
        WH + (size_t)1536*512, 0, hhH, PXS, 512,
        bo, nullptr, x, out, nullptr, nullptr, 0.f);
}